// round 6
// baseline (speedup 1.0000x reference)
#include <cuda_runtime.h>
#include <cstdint>

#define N_SIG 32768
#define KDIM  512
#define DDIM  64
#define NNZ   4
#define REGEPS 1e-7f

// Output tuple layout (flat f32):
#define OUT_OFF   0ll         // [8,64,64,64]  = 2097152
#define DIFF1_OFF 2097152ll
#define DIFF2_OFF 2097153ll
#define IDS_OFF   2097154ll   // [8,512,64,64] = 16777216
#define NSTEP_OFF 18874370ll
#define MEAND_OFF 18874371ll
#define MEANZ_OFF 18874372ll
#define NORMZ_OFF 18874373ll
#define TOPP_OFF  18874374ll
#define NZERO_OFF 18874375ll

// ---------------- scratch (no allocation allowed) ----------------
__device__ float g_Dn[DDIM*KDIM];
__device__ float g_DnT[KDIM*DDIM];
__device__ float g_G[KDIM*KDIM];
__device__ float g_xt[(size_t)N_SIG*DDIM];
__device__ float g_qt[(size_t)N_SIG*DDIM];
__device__ float g_alpha0[(size_t)N_SIG*KDIM];   // 64MB hand-off
__device__ float g_diffsum, g_zsum, g_meanDsum;
__device__ int   g_hist[5];

// ---------------- helpers ----------------
__device__ __forceinline__ unsigned long long ffma2(unsigned long long a,
                                                    unsigned long long b,
                                                    unsigned long long c) {
    unsigned long long d;
    asm("fma.rn.f32x2 %0, %1, %2, %3;" : "=l"(d) : "l"(a), "l"(b), "l"(c));
    return d;
}
__device__ __forceinline__ unsigned long long packdup(float v) {
    unsigned long long r;
    asm("mov.b64 %0, {%1, %1};" : "=l"(r) : "f"(v));
    return r;
}
__device__ __forceinline__ float sel16(const float a[16], int t) {
    float r = a[0];
    #pragma unroll
    for (int i = 1; i < 16; i++) if (t == i) r = a[i];
    return r;
}

// ---------------- fused prep + Gram ----------------
// Each of 32 blocks loads D into smem, normalizes (redundant), computes 16 rows
// of G = Dn^T Dn. Block 0 additionally writes g_Dn, g_DnT, mean|Dn|, and zeros
// the accumulators.
__global__ __launch_bounds__(256, 1) void prepgram_kernel(const float* __restrict__ D) {
    extern __shared__ float sd[];  // 64*512 floats = 128KB
    __shared__ float red[256];
    int t = threadIdx.x;
    for (int i = t; i < DDIM*KDIM; i += 256) sd[i] = D[i];
    __syncthreads();
    // normalize: thread t owns columns t and t+256
    float asum_loc = 0.f;
    #pragma unroll
    for (int half = 0; half < 2; half++) {
        int k = t + half*256;
        float ss = 0.f;
        #pragma unroll 8
        for (int d = 0; d < DDIM; d++) { float v = sd[d*KDIM + k]; ss += v*v; }
        float inv = rsqrtf(ss);
        // match reference 1/sqrt exactly: use division form
        inv = 1.0f / sqrtf(ss);
        #pragma unroll 8
        for (int d = 0; d < DDIM; d++) {
            float v = sd[d*KDIM + k] * inv;
            sd[d*KDIM + k] = v;
            asum_loc += fabsf(v);
        }
    }
    __syncthreads();

    // Gram rows [r0, r0+16)
    int r0 = blockIdx.x * 16;
    #pragma unroll 1
    for (int jp = 0; jp < 2; jp++) {
        int j = t + jp*256;
        float a[16];
        #pragma unroll
        for (int r = 0; r < 16; r++) a[r] = 0.f;
        #pragma unroll 4
        for (int d = 0; d < DDIM; d++) {
            float cj = sd[d*KDIM + j];
            #pragma unroll
            for (int r = 0; r < 16; r++) a[r] += sd[d*KDIM + r0 + r] * cj;
        }
        #pragma unroll
        for (int r = 0; r < 16; r++) g_G[(size_t)(r0 + r)*KDIM + j] = a[r];
    }

    if (blockIdx.x == 0) {
        // write Dn (coalesced) and DnT (transposed)
        for (int i = t; i < DDIM*KDIM; i += 256) g_Dn[i] = sd[i];
        #pragma unroll
        for (int half = 0; half < 2; half++) {
            int k = t + half*256;
            #pragma unroll 8
            for (int d = 0; d < DDIM; d++) g_DnT[k*DDIM + d] = sd[d*KDIM + k];
        }
        red[t] = asum_loc; __syncthreads();
        for (int off = 128; off > 0; off >>= 1) {
            if (t < off) red[t] += red[t + off];
            __syncthreads();
        }
        if (t == 0) {
            g_meanDsum = red[0];
            g_diffsum = 0.f; g_zsum = 0.f;
        }
        if (t < 5) g_hist[t] = 0;
    }
}

// ---------------- transpose x [B,DIM,H,W] -> x_t [N,DIM] ----------------
__global__ void xt_kernel(const float* __restrict__ x) {
    __shared__ float tile[32][33];
    int b   = blockIdx.z;
    int hw0 = blockIdx.x * 32;
    int d0  = blockIdx.y * 32;
    int tx = threadIdx.x, ty = threadIdx.y;
    #pragma unroll
    for (int i = 0; i < 4; i++) {
        int d = d0 + ty + i*8;
        tile[ty + i*8][tx] = x[(size_t)(b*DDIM + d)*4096 + hw0 + tx];
    }
    __syncthreads();
    #pragma unroll
    for (int i = 0; i < 4; i++) {
        int hw = hw0 + ty + i*8;
        g_xt[(size_t)(b*4096 + hw)*DDIM + d0 + tx] = tile[tx][ty + i*8];
    }
}

// ---------------- transpose q_t [N,DIM] -> out [B,DIM,H,W] ----------------
__global__ void outt_kernel(float* __restrict__ out) {
    __shared__ float tile[32][33];
    int b   = blockIdx.z;
    int hw0 = blockIdx.x * 32;
    int d0  = blockIdx.y * 32;
    int tx = threadIdx.x, ty = threadIdx.y;
    #pragma unroll
    for (int i = 0; i < 4; i++) {
        int hw = hw0 + ty + i*8;
        tile[ty + i*8][tx] = g_qt[(size_t)(b*4096 + hw)*DDIM + d0 + tx];
    }
    __syncthreads();
    #pragma unroll
    for (int i = 0; i < 4; i++) {
        int d = d0 + ty + i*8;
        out[(size_t)(b*DDIM + d)*4096 + hw0 + tx] = tile[tx][ty + i*8];
    }
}

// ---------------- Kernel A: alpha0 = X * Dn (packed f32x2 GEMV) ----------------
#define A_THREADS 512
#define A_WARPS   16
#define SMEM_DN_BYTES (DDIM*KDIM*4)                 // 131072
#define SMEM_X_OFF    SMEM_DN_BYTES
#define SMEM_X_BYTES  (A_WARPS*4*DDIM*8)            // 32768
#define SMEM_A_TOTAL  (SMEM_X_OFF + SMEM_X_BYTES)

__global__ __launch_bounds__(A_THREADS, 1)
void alpha_kernel() {
    extern __shared__ unsigned char smraw[];
    float* sDn = (float*)smraw;
    unsigned long long* sX = (unsigned long long*)(smraw + SMEM_X_OFF);

    int tid  = threadIdx.x;
    int lane = tid & 31;
    int w    = tid >> 5;
    for (int i = tid; i < DDIM*KDIM; i += A_THREADS) sDn[i] = g_Dn[i];
    __syncthreads();

    unsigned long long* xw = sX + w * 4 * DDIM;
    const ulonglong2* sDn2 = (const ulonglong2*)sDn;

    int gw = blockIdx.x * A_WARPS + w;
    int nw = gridDim.x * A_WARPS;
    for (int g = gw; g < N_SIG/4; g += nw) {
        int n0 = g * 4;
        __syncwarp();
        #pragma unroll
        for (int s = 0; s < 4; s++) {
            const float* xp = g_xt + (size_t)(n0 + s) * DDIM;
            xw[s*DDIM + lane]      = packdup(xp[lane]);
            xw[s*DDIM + lane + 32] = packdup(xp[lane + 32]);
        }
        __syncwarp();

        unsigned long long acc[4][8];
        #pragma unroll
        for (int s = 0; s < 4; s++)
            #pragma unroll
            for (int t = 0; t < 8; t++) acc[s][t] = 0ull;

        #pragma unroll 2
        for (int d = 0; d < DDIM; d++) {
            unsigned long long xd[4];
            #pragma unroll
            for (int s = 0; s < 4; s++) xd[s] = xw[s*DDIM + d];
            #pragma unroll
            for (int c2 = 0; c2 < 4; c2++) {
                ulonglong2 q = sDn2[d*128 + c2*32 + lane];
                #pragma unroll
                for (int s = 0; s < 4; s++) {
                    acc[s][c2*2]     = ffma2(q.x, xd[s], acc[s][c2*2]);
                    acc[s][c2*2 + 1] = ffma2(q.y, xd[s], acc[s][c2*2 + 1]);
                }
            }
        }

        // store: float index n*512 + c2*128 + lane*4 (+0..3)
        #pragma unroll
        for (int s = 0; s < 4; s++) {
            ulonglong2* ap = (ulonglong2*)(g_alpha0 + (size_t)(n0 + s) * KDIM);
            #pragma unroll
            for (int c2 = 0; c2 < 4; c2++) {
                ulonglong2 v; v.x = acc[s][c2*2]; v.y = acc[s][c2*2 + 1];
                ap[c2*32 + lane] = v;
            }
        }
    }
}

// ---------------- Kernel B: OMP iterations, 1 signal per warp ----------------
#define B_THREADS 256
#define B_WARPS   8
#define B_BLOCKS  1024   // 8192 warps x 4 signals = 32768

__global__ __launch_bounds__(B_THREADS)
void ompsel_kernel(float* __restrict__ out) {
    __shared__ float sAccF[2];
    __shared__ int   sHist[5];
    int tid  = threadIdx.x;
    int lane = tid & 31;
    int w    = tid >> 5;
    if (tid < 2) sAccF[tid] = 0.f;
    if (tid < 5) sHist[tid] = 0;
    __syncthreads();

    float diffacc = 0.f, zacc = 0.f;
    int h0 = 0, h1 = 0, h2 = 0, h3 = 0, h4 = 0;

    int gw = blockIdx.x * B_WARPS + w;
    #pragma unroll 1
    for (int s4 = 0; s4 < 4; s4++) {
        int n = gw * 4 + s4;

        // load alpha0: a0[c2*4+j] holds k = c2*128 + lane*4 + j
        const float4* ap = (const float4*)(g_alpha0 + (size_t)n * KDIM);
        float a0[16];
        #pragma unroll
        for (int c2 = 0; c2 < 4; c2++) {
            float4 q = __ldg(ap + c2*32 + lane);
            a0[c2*4 + 0] = q.x; a0[c2*4 + 1] = q.y;
            a0[c2*4 + 2] = q.z; a0[c2*4 + 3] = q.w;
        }

        int idx[4]; float gam[4]; float rhs[4]; float Ms[4][4];
        #pragma unroll
        for (int r = 0; r < 4; r++)
            #pragma unroll
            for (int c = 0; c < 4; c++) Ms[r][c] = 0.f;

        #pragma unroll
        for (int it = 0; it < NNZ; it++) {
            // alpha = alpha0 - sum_p gam[p]*G[idx[p],:]
            float vv[16];
            #pragma unroll
            for (int t = 0; t < 16; t++) vv[t] = a0[t];
            #pragma unroll
            for (int p = 0; p < NNZ - 1; p++) if (p < it) {
                const float4* Gr = (const float4*)(g_G + (size_t)idx[p]*KDIM);
                float gp = gam[p];
                #pragma unroll
                for (int c2 = 0; c2 < 4; c2++) {
                    float4 gq = __ldg(Gr + c2*32 + lane);
                    vv[c2*4 + 0] -= gp * gq.x;
                    vv[c2*4 + 1] -= gp * gq.y;
                    vv[c2*4 + 2] -= gp * gq.z;
                    vv[c2*4 + 3] -= gp * gq.w;
                }
            }
            // argmax |alpha| (first-index tie-break)
            float bv = -1.f; int bk = 0;
            #pragma unroll
            for (int t = 0; t < 16; t++) {
                int k = ((t >> 2) << 7) | (lane << 2) | (t & 3);
                float av = fabsf(vv[t]);
                if (av > bv) { bv = av; bk = k; }
            }
            #pragma unroll
            for (int off = 16; off > 0; off >>= 1) {
                float ov = __shfl_xor_sync(0xffffffffu, bv, off);
                int   ok = __shfl_xor_sync(0xffffffffu, bk, off);
                if (ov > bv || (ov == bv && ok < bk)) { bv = ov; bk = ok; }
            }
            idx[it] = bk;
            // rhs[it] = alpha0[bk]
            int tt = (((bk >> 7) & 3) << 2) | (bk & 3);
            float myv = sel16(a0, tt);
            rhs[it] = __shfl_sync(0xffffffffu, myv, (bk >> 2) & 31);
            // extend G_sub
            #pragma unroll
            for (int b2 = 0; b2 < NNZ; b2++) if (b2 <= it) {
                float gv = __ldg(g_G + (size_t)bk*KDIM + idx[b2]);
                Ms[it][b2] = gv; Ms[b2][it] = gv;
            }
            // solve (it+1)x(it+1) SPD system (G_sub + eps*I) gamma = rhs
            {
                float M[4][4], yv[4], gv2[4];
                #pragma unroll
                for (int r = 0; r < 4; r++) {
                    #pragma unroll
                    for (int c = 0; c < 4; c++) M[r][c] = Ms[r][c];
                    M[r][r] += REGEPS;
                    yv[r] = rhs[r];
                    gv2[r] = 0.f;
                }
                #pragma unroll
                for (int c = 0; c < 4; c++) if (c <= it) {
                    float pinv = 1.f / M[c][c];
                    #pragma unroll
                    for (int r = 0; r < 4; r++) if (r > c && r <= it) {
                        float f = M[r][c] * pinv;
                        #pragma unroll
                        for (int cc = 0; cc < 4; cc++) if (cc >= c && cc <= it)
                            M[r][cc] -= f * M[c][cc];
                        yv[r] -= f * yv[c];
                    }
                }
                #pragma unroll
                for (int r = 3; r >= 0; r--) if (r <= it) {
                    float a2 = yv[r];
                    #pragma unroll
                    for (int cc = 0; cc < 4; cc++) if (cc > r && cc <= it)
                        a2 -= M[r][cc] * gv2[cc];
                    gv2[r] = a2 / M[r][r];
                }
                #pragma unroll
                for (int r = 0; r < 4; r++) if (r <= it) gam[r] = gv2[r];
            }
        }

        // duplicate handling: final cell value = gamma of LAST occurrence
        bool lastocc[4];
        #pragma unroll
        for (int a = 0; a < 4; a++) {
            bool lo2 = true;
            #pragma unroll
            for (int b2 = a + 1; b2 < 4; b2++) if (idx[b2] == idx[a]) lo2 = false;
            lastocc[a] = lo2;
        }

        // quant = code @ Dn^T (DnT rows L2-resident)
        float q0 = 0.f, q1 = 0.f;
        #pragma unroll
        for (int a = 0; a < 4; a++) if (lastocc[a]) {
            const float* dt = g_DnT + (size_t)idx[a]*DDIM;
            q0 += gam[a] * __ldg(dt + lane);
            q1 += gam[a] * __ldg(dt + lane + 32);
        }
        g_qt[(size_t)n*DDIM + lane]      = q0;
        g_qt[(size_t)n*DDIM + lane + 32] = q1;
        const float* xp = g_xt + (size_t)n * DDIM;
        float xv0 = __ldg(xp + lane);
        float xv1 = __ldg(xp + lane + 32);
        diffacc += (q0 - xv0)*(q0 - xv0) + (q1 - xv1)*(q1 - xv1);

        if (lane == 0) {
            int b = n >> 12, hw = n & 4095;
            float* ids = out + IDS_OFF + (size_t)b*(KDIM*4096) + hw;
            int cnt = 0;
            #pragma unroll
            for (int a = 0; a < 4; a++) {
                ids[(size_t)idx[a]*4096] = gam[a];  // program order: last write wins
                if (lastocc[a] && gam[a] != 0.f) { cnt++; zacc += fabsf(gam[a]); }
            }
            if (cnt == 0) h0++; else if (cnt == 1) h1++; else if (cnt == 2) h2++;
            else if (cnt == 3) h3++; else h4++;
        }
    }

    // ---- reductions ----
    #pragma unroll
    for (int off = 16; off > 0; off >>= 1) {
        diffacc += __shfl_xor_sync(0xffffffffu, diffacc, off);
        zacc    += __shfl_xor_sync(0xffffffffu, zacc, off);
    }
    if (lane == 0) {
        atomicAdd(&sAccF[0], diffacc);
        atomicAdd(&sAccF[1], zacc);
        if (h0) atomicAdd(&sHist[0], h0);
        if (h1) atomicAdd(&sHist[1], h1);
        if (h2) atomicAdd(&sHist[2], h2);
        if (h3) atomicAdd(&sHist[3], h3);
        if (h4) atomicAdd(&sHist[4], h4);
    }
    __syncthreads();
    if (tid == 0) {
        atomicAdd(&g_diffsum, sAccF[0]);
        atomicAdd(&g_zsum, sAccF[1]);
    }
    if (tid < 5) { int v = sHist[tid]; if (v) atomicAdd(&g_hist[tid], v); }
}

// ---------------- finalize scalars ----------------
__global__ void fin_kernel(float* __restrict__ out) {
    if (threadIdx.x != 0) return;
    float diff = g_diffsum / 2097152.0f;
    out[DIFF1_OFF] = diff;
    out[DIFF2_OFF] = diff;
    out[NSTEP_OFF] = 4.0f;
    out[MEAND_OFF] = g_meanDsum / 32768.0f;
    out[MEANZ_OFF] = g_zsum / 16777216.0f;
    int c0 = g_hist[0], c1 = g_hist[1], c2 = g_hist[2], c3 = g_hist[3], c4 = g_hist[4];
    float sumw = 1.f*c1 + 2.f*c2 + 3.f*c3 + 4.f*c4;
    out[NORMZ_OFF] = sumw / 32768.0f;
    const int topk = 327;  // int(32768 * 0.01)
    int cum = c4; float tp = 4.f;
    if (cum < topk) { cum += c3; tp = 3.f; }
    if (cum < topk) { cum += c2; tp = 2.f; }
    if (cum < topk) { cum += c1; tp = 1.f; }
    if (cum < topk) { tp = 0.f; }
    out[TOPP_OFF]  = tp;
    out[NZERO_OFF] = (float)c0;
}

// ---------------- launch ----------------
extern "C" void kernel_launch(void* const* d_in, const int* in_sizes, int n_in,
                              void* d_out, int out_size) {
    const float* x; const float* D;
    if (in_sizes[0] == DDIM*KDIM) { D = (const float*)d_in[0]; x = (const float*)d_in[1]; }
    else                          { x = (const float*)d_in[0]; D = (const float*)d_in[1]; }
    float* out = (float*)d_out;

    cudaFuncSetAttribute(prepgram_kernel, cudaFuncAttributeMaxDynamicSharedMemorySize, SMEM_DN_BYTES);
    prepgram_kernel<<<32, 256, SMEM_DN_BYTES>>>(D);
    xt_kernel<<<dim3(128, 2, 8), dim3(32, 8)>>>(x);
    cudaMemsetAsync(out + IDS_OFF, 0, (size_t)16777216 * sizeof(float));
    cudaFuncSetAttribute(alpha_kernel, cudaFuncAttributeMaxDynamicSharedMemorySize, SMEM_A_TOTAL);
    alpha_kernel<<<152, A_THREADS, SMEM_A_TOTAL>>>();
    ompsel_kernel<<<B_BLOCKS, B_THREADS>>>(out);
    outt_kernel<<<dim3(128, 2, 8), dim3(32, 8)>>>(out);
    fin_kernel<<<1, 32>>>(out);
}

// round 8
// speedup vs baseline: 1.0395x; 1.0395x over previous
#include <cuda_runtime.h>
#include <cstdint>

#define N_SIG 32768
#define KDIM  512
#define DDIM  64
#define NNZ   4
#define REGEPS 1e-7f

// Output tuple layout (flat f32):
#define OUT_OFF   0ll         // [8,64,64,64]  = 2097152
#define DIFF1_OFF 2097152ll
#define DIFF2_OFF 2097153ll
#define IDS_OFF   2097154ll   // [8,512,64,64] = 16777216
#define NSTEP_OFF 18874370ll
#define MEAND_OFF 18874371ll
#define MEANZ_OFF 18874372ll
#define NORMZ_OFF 18874373ll
#define TOPP_OFF  18874374ll
#define NZERO_OFF 18874375ll

// ---------------- scratch (no allocation allowed) ----------------
__device__ float g_Dn[DDIM*KDIM];
__device__ float g_DnT[KDIM*DDIM];
__device__ float g_G[KDIM*KDIM];
__device__ float g_xt[(size_t)N_SIG*DDIM];
__device__ float g_qt[(size_t)N_SIG*DDIM];
__device__ float g_alpha0[(size_t)N_SIG*KDIM];   // 64MB hand-off
__device__ float g_diffsum, g_zsum, g_meanDsum;
__device__ int   g_hist[5];

// ---------------- helpers ----------------
__device__ __forceinline__ unsigned long long ffma2(unsigned long long a,
                                                    unsigned long long b,
                                                    unsigned long long c) {
    unsigned long long d;
    asm("fma.rn.f32x2 %0, %1, %2, %3;" : "=l"(d) : "l"(a), "l"(b), "l"(c));
    return d;
}
__device__ __forceinline__ unsigned long long packdup(float v) {
    unsigned long long r;
    asm("mov.b64 %0, {%1, %1};" : "=l"(r) : "f"(v));
    return r;
}
__device__ __forceinline__ float sel16(const float a[16], int t) {
    float r = a[0];
    #pragma unroll
    for (int i = 1; i < 16; i++) if (t == i) r = a[i];
    return r;
}

// ---------------- fused prep + Gram ----------------
__global__ __launch_bounds__(256, 1) void prepgram_kernel(const float* __restrict__ D) {
    extern __shared__ float sd[];  // 64*512 floats = 128KB
    __shared__ float red[256];
    int t = threadIdx.x;
    for (int i = t; i < DDIM*KDIM; i += 256) sd[i] = D[i];
    __syncthreads();
    // normalize: thread t owns columns t and t+256
    float asum_loc = 0.f;
    #pragma unroll
    for (int half = 0; half < 2; half++) {
        int k = t + half*256;
        float ss = 0.f;
        #pragma unroll 8
        for (int d = 0; d < DDIM; d++) { float v = sd[d*KDIM + k]; ss += v*v; }
        float inv = 1.0f / sqrtf(ss);
        #pragma unroll 8
        for (int d = 0; d < DDIM; d++) {
            float v = sd[d*KDIM + k] * inv;
            sd[d*KDIM + k] = v;
            asum_loc += fabsf(v);
        }
    }
    __syncthreads();

    // Gram rows [r0, r0+16)
    int r0 = blockIdx.x * 16;
    #pragma unroll 1
    for (int jp = 0; jp < 2; jp++) {
        int j = t + jp*256;
        float a[16];
        #pragma unroll
        for (int r = 0; r < 16; r++) a[r] = 0.f;
        #pragma unroll 4
        for (int d = 0; d < DDIM; d++) {
            float cj = sd[d*KDIM + j];
            #pragma unroll
            for (int r = 0; r < 16; r++) a[r] += sd[d*KDIM + r0 + r] * cj;
        }
        #pragma unroll
        for (int r = 0; r < 16; r++) g_G[(size_t)(r0 + r)*KDIM + j] = a[r];
    }

    if (blockIdx.x == 0) {
        for (int i = t; i < DDIM*KDIM; i += 256) g_Dn[i] = sd[i];
        #pragma unroll
        for (int half = 0; half < 2; half++) {
            int k = t + half*256;
            #pragma unroll 8
            for (int d = 0; d < DDIM; d++) g_DnT[k*DDIM + d] = sd[d*KDIM + k];
        }
        red[t] = asum_loc; __syncthreads();
        for (int off = 128; off > 0; off >>= 1) {
            if (t < off) red[t] += red[t + off];
            __syncthreads();
        }
        if (t == 0) {
            g_meanDsum = red[0];
            g_diffsum = 0.f; g_zsum = 0.f;
        }
        if (t < 5) g_hist[t] = 0;
    }
}

// ---------------- transpose x [B,DIM,H,W] -> x_t [N,DIM] ----------------
__global__ void xt_kernel(const float* __restrict__ x) {
    __shared__ float tile[32][33];
    int b   = blockIdx.z;
    int hw0 = blockIdx.x * 32;
    int d0  = blockIdx.y * 32;
    int tx = threadIdx.x, ty = threadIdx.y;
    #pragma unroll
    for (int i = 0; i < 4; i++) {
        int d = d0 + ty + i*8;
        tile[ty + i*8][tx] = x[(size_t)(b*DDIM + d)*4096 + hw0 + tx];
    }
    __syncthreads();
    #pragma unroll
    for (int i = 0; i < 4; i++) {
        int hw = hw0 + ty + i*8;
        g_xt[(size_t)(b*4096 + hw)*DDIM + d0 + tx] = tile[tx][ty + i*8];
    }
}

// ---------------- transpose q_t [N,DIM] -> out [B,DIM,H,W] ----------------
__global__ void outt_kernel(float* __restrict__ out) {
    __shared__ float tile[32][33];
    int b   = blockIdx.z;
    int hw0 = blockIdx.x * 32;
    int d0  = blockIdx.y * 32;
    int tx = threadIdx.x, ty = threadIdx.y;
    #pragma unroll
    for (int i = 0; i < 4; i++) {
        int hw = hw0 + ty + i*8;
        tile[ty + i*8][tx] = g_qt[(size_t)(b*4096 + hw)*DDIM + d0 + tx];
    }
    __syncthreads();
    #pragma unroll
    for (int i = 0; i < 4; i++) {
        int d = d0 + ty + i*8;
        out[(size_t)(b*DDIM + d)*4096 + hw0 + tx] = tile[tx][ty + i*8];
    }
}

// ---------------- Kernel A: alpha0 = X * Dn, 8 signals/warp, prefetched ------
#define A_THREADS 256
#define A_WARPS   8
#define A_SIG     8
#define A_NGRP    (N_SIG / A_SIG)                   // 4096
#define SMEM_DN_BYTES (DDIM*KDIM*4)                 // 131072
#define SMEM_X_OFF    SMEM_DN_BYTES
#define SMEM_X_BYTES  (A_WARPS*A_SIG*DDIM*8)       // 32768
#define SMEM_A_TOTAL  (SMEM_X_OFF + SMEM_X_BYTES)

__global__ __launch_bounds__(A_THREADS, 1)
void alpha_kernel() {
    extern __shared__ unsigned char smraw[];
    float* sDn = (float*)smraw;
    unsigned long long* sX = (unsigned long long*)(smraw + SMEM_X_OFF);

    int tid  = threadIdx.x;
    int lane = tid & 31;
    int w    = tid >> 5;
    for (int i = tid; i < DDIM*KDIM; i += A_THREADS) sDn[i] = g_Dn[i];
    __syncthreads();

    unsigned long long* xw = sX + w * A_SIG * DDIM;
    const ulonglong2* sDn2 = (const ulonglong2*)sDn;

    int gw = blockIdx.x * A_WARPS + w;
    int nw = gridDim.x * A_WARPS;

    // prefetch first group's x into registers
    float xf[2*A_SIG];
    if (gw < A_NGRP) {
        #pragma unroll
        for (int s = 0; s < A_SIG; s++) {
            const float* xp = g_xt + (size_t)(gw*A_SIG + s) * DDIM;
            xf[2*s]     = __ldg(xp + lane);
            xf[2*s + 1] = __ldg(xp + lane + 32);
        }
    }

    #pragma unroll 1
    for (int g = gw; g < A_NGRP; g += nw) {
        // stage prefetched x into smem (packed-dup for f32x2)
        __syncwarp();
        #pragma unroll
        for (int s = 0; s < A_SIG; s++) {
            xw[s*DDIM + lane]      = packdup(xf[2*s]);
            xw[s*DDIM + lane + 32] = packdup(xf[2*s + 1]);
        }
        __syncwarp();
        // prefetch next group while computing this one
        int g2 = g + nw;
        if (g2 < A_NGRP) {
            #pragma unroll
            for (int s = 0; s < A_SIG; s++) {
                const float* xp = g_xt + (size_t)(g2*A_SIG + s) * DDIM;
                xf[2*s]     = __ldg(xp + lane);
                xf[2*s + 1] = __ldg(xp + lane + 32);
            }
        }

        unsigned long long acc[A_SIG][8];
        #pragma unroll
        for (int s = 0; s < A_SIG; s++)
            #pragma unroll
            for (int t = 0; t < 8; t++) acc[s][t] = 0ull;

        #pragma unroll 2
        for (int d = 0; d < DDIM; d++) {
            unsigned long long xd[A_SIG];
            #pragma unroll
            for (int s = 0; s < A_SIG; s++) xd[s] = xw[s*DDIM + d];
            #pragma unroll
            for (int c2 = 0; c2 < 4; c2++) {
                ulonglong2 q = sDn2[d*128 + c2*32 + lane];
                #pragma unroll
                for (int s = 0; s < A_SIG; s++) {
                    acc[s][c2*2]     = ffma2(q.x, xd[s], acc[s][c2*2]);
                    acc[s][c2*2 + 1] = ffma2(q.y, xd[s], acc[s][c2*2 + 1]);
                }
            }
        }

        // store: float index n*512 + c2*128 + lane*4 (+0..3)
        #pragma unroll
        for (int s = 0; s < A_SIG; s++) {
            ulonglong2* ap = (ulonglong2*)(g_alpha0 + (size_t)(g*A_SIG + s) * KDIM);
            #pragma unroll
            for (int c2 = 0; c2 < 4; c2++) {
                ulonglong2 v; v.x = acc[s][c2*2]; v.y = acc[s][c2*2 + 1];
                ap[c2*32 + lane] = v;
            }
        }
    }
}

// ---------------- Kernel B: OMP iterations, 1 signal per warp ----------------
#define B_THREADS 256
#define B_WARPS   8
#define B_BLOCKS  1024   // 8192 warps x 4 signals = 32768

__global__ __launch_bounds__(B_THREADS, 3)
void ompsel_kernel(float* __restrict__ out) {
    __shared__ float sAccF[2];
    __shared__ int   sHist[5];
    int tid  = threadIdx.x;
    int lane = tid & 31;
    int w    = tid >> 5;
    if (tid < 2) sAccF[tid] = 0.f;
    if (tid < 5) sHist[tid] = 0;
    __syncthreads();

    float diffacc = 0.f, zacc = 0.f;
    int h0 = 0, h1 = 0, h2 = 0, h3 = 0, h4 = 0;

    int gw = blockIdx.x * B_WARPS + w;
    #pragma unroll 1
    for (int s4 = 0; s4 < 4; s4++) {
        int n = gw * 4 + s4;

        // load alpha0: a0[c2*4+j] holds k = c2*128 + lane*4 + j
        const float4* ap = (const float4*)(g_alpha0 + (size_t)n * KDIM);
        float a0[16];
        #pragma unroll
        for (int c2 = 0; c2 < 4; c2++) {
            float4 q = __ldg(ap + c2*32 + lane);
            a0[c2*4 + 0] = q.x; a0[c2*4 + 1] = q.y;
            a0[c2*4 + 2] = q.z; a0[c2*4 + 3] = q.w;
        }

        int idx[4]; float gam[4]; float rhs[4]; float Ms[4][4];
        #pragma unroll
        for (int r = 0; r < 4; r++)
            #pragma unroll
            for (int c = 0; c < 4; c++) Ms[r][c] = 0.f;

        #pragma unroll
        for (int it = 0; it < NNZ; it++) {
            // alpha = alpha0 - sum_p gam[p]*G[idx[p],:]
            float vv[16];
            #pragma unroll
            for (int t = 0; t < 16; t++) vv[t] = a0[t];
            #pragma unroll
            for (int p = 0; p < NNZ - 1; p++) if (p < it) {
                const float4* Gr = (const float4*)(g_G + (size_t)idx[p]*KDIM);
                float gp = gam[p];
                #pragma unroll
                for (int c2 = 0; c2 < 4; c2++) {
                    float4 gq = __ldg(Gr + c2*32 + lane);
                    vv[c2*4 + 0] -= gp * gq.x;
                    vv[c2*4 + 1] -= gp * gq.y;
                    vv[c2*4 + 2] -= gp * gq.z;
                    vv[c2*4 + 3] -= gp * gq.w;
                }
            }
            // argmax |alpha| (first-index tie-break)
            float bv = -1.f; int bk = 0;
            #pragma unroll
            for (int t = 0; t < 16; t++) {
                int k = ((t >> 2) << 7) | (lane << 2) | (t & 3);
                float av = fabsf(vv[t]);
                if (av > bv) { bv = av; bk = k; }
            }
            #pragma unroll
            for (int off = 16; off > 0; off >>= 1) {
                float ov = __shfl_xor_sync(0xffffffffu, bv, off);
                int   ok = __shfl_xor_sync(0xffffffffu, bk, off);
                if (ov > bv || (ov == bv && ok < bk)) { bv = ov; bk = ok; }
            }
            idx[it] = bk;
            // rhs[it] = alpha0[bk]
            int tt = (((bk >> 7) & 3) << 2) | (bk & 3);
            float myv = sel16(a0, tt);
            rhs[it] = __shfl_sync(0xffffffffu, myv, (bk >> 2) & 31);
            // extend G_sub
            #pragma unroll
            for (int b2 = 0; b2 < NNZ; b2++) if (b2 <= it) {
                float gv = __ldg(g_G + (size_t)bk*KDIM + idx[b2]);
                Ms[it][b2] = gv; Ms[b2][it] = gv;
            }
            // solve (it+1)x(it+1) SPD system (G_sub + eps*I) gamma = rhs
            {
                float M[4][4], yv[4], gv2[4];
                #pragma unroll
                for (int r = 0; r < 4; r++) {
                    #pragma unroll
                    for (int c = 0; c < 4; c++) M[r][c] = Ms[r][c];
                    M[r][r] += REGEPS;
                    yv[r] = rhs[r];
                    gv2[r] = 0.f;
                }
                #pragma unroll
                for (int c = 0; c < 4; c++) if (c <= it) {
                    float pinv = 1.f / M[c][c];
                    #pragma unroll
                    for (int r = 0; r < 4; r++) if (r > c && r <= it) {
                        float f = M[r][c] * pinv;
                        #pragma unroll
                        for (int cc = 0; cc < 4; cc++) if (cc >= c && cc <= it)
                            M[r][cc] -= f * M[c][cc];
                        yv[r] -= f * yv[c];
                    }
                }
                #pragma unroll
                for (int r = 3; r >= 0; r--) if (r <= it) {
                    float a2 = yv[r];
                    #pragma unroll
                    for (int cc = 0; cc < 4; cc++) if (cc > r && cc <= it)
                        a2 -= M[r][cc] * gv2[cc];
                    gv2[r] = a2 / M[r][r];
                }
                #pragma unroll
                for (int r = 0; r < 4; r++) if (r <= it) gam[r] = gv2[r];
            }
        }

        // duplicate handling: final cell value = gamma of LAST occurrence
        bool lastocc[4];
        #pragma unroll
        for (int a = 0; a < 4; a++) {
            bool lo2 = true;
            #pragma unroll
            for (int b2 = a + 1; b2 < 4; b2++) if (idx[b2] == idx[a]) lo2 = false;
            lastocc[a] = lo2;
        }

        // quant = code @ Dn^T (DnT rows L2-resident)
        float q0 = 0.f, q1 = 0.f;
        #pragma unroll
        for (int a = 0; a < 4; a++) if (lastocc[a]) {
            const float* dt = g_DnT + (size_t)idx[a]*DDIM;
            q0 += gam[a] * __ldg(dt + lane);
            q1 += gam[a] * __ldg(dt + lane + 32);
        }
        g_qt[(size_t)n*DDIM + lane]      = q0;
        g_qt[(size_t)n*DDIM + lane + 32] = q1;
        const float* xp = g_xt + (size_t)n * DDIM;
        float xv0 = __ldg(xp + lane);
        float xv1 = __ldg(xp + lane + 32);
        diffacc += (q0 - xv0)*(q0 - xv0) + (q1 - xv1)*(q1 - xv1);

        if (lane == 0) {
            int b = n >> 12, hw = n & 4095;
            float* ids = out + IDS_OFF + (size_t)b*(KDIM*4096) + hw;
            int cnt = 0;
            #pragma unroll
            for (int a = 0; a < 4; a++) {
                ids[(size_t)idx[a]*4096] = gam[a];  // program order: last write wins
                if (lastocc[a] && gam[a] != 0.f) { cnt++; zacc += fabsf(gam[a]); }
            }
            if (cnt == 0) h0++; else if (cnt == 1) h1++; else if (cnt == 2) h2++;
            else if (cnt == 3) h3++; else h4++;
        }
    }

    // ---- reductions ----
    #pragma unroll
    for (int off = 16; off > 0; off >>= 1) {
        diffacc += __shfl_xor_sync(0xffffffffu, diffacc, off);
        zacc    += __shfl_xor_sync(0xffffffffu, zacc, off);
    }
    if (lane == 0) {
        atomicAdd(&sAccF[0], diffacc);
        atomicAdd(&sAccF[1], zacc);
        if (h0) atomicAdd(&sHist[0], h0);
        if (h1) atomicAdd(&sHist[1], h1);
        if (h2) atomicAdd(&sHist[2], h2);
        if (h3) atomicAdd(&sHist[3], h3);
        if (h4) atomicAdd(&sHist[4], h4);
    }
    __syncthreads();
    if (tid == 0) {
        atomicAdd(&g_diffsum, sAccF[0]);
        atomicAdd(&g_zsum, sAccF[1]);
    }
    if (tid < 5) { int v = sHist[tid]; if (v) atomicAdd(&g_hist[tid], v); }
}

// ---------------- finalize scalars ----------------
__global__ void fin_kernel(float* __restrict__ out) {
    if (threadIdx.x != 0) return;
    float diff = g_diffsum / 2097152.0f;
    out[DIFF1_OFF] = diff;
    out[DIFF2_OFF] = diff;
    out[NSTEP_OFF] = 4.0f;
    out[MEAND_OFF] = g_meanDsum / 32768.0f;
    out[MEANZ_OFF] = g_zsum / 16777216.0f;
    int c0 = g_hist[0], c1 = g_hist[1], c2 = g_hist[2], c3 = g_hist[3], c4 = g_hist[4];
    float sumw = 1.f*c1 + 2.f*c2 + 3.f*c3 + 4.f*c4;
    out[NORMZ_OFF] = sumw / 32768.0f;
    const int topk = 327;  // int(32768 * 0.01)
    int cum = c4; float tp = 4.f;
    if (cum < topk) { cum += c3; tp = 3.f; }
    if (cum < topk) { cum += c2; tp = 2.f; }
    if (cum < topk) { cum += c1; tp = 1.f; }
    if (cum < topk) { tp = 0.f; }
    out[TOPP_OFF]  = tp;
    out[NZERO_OFF] = (float)c0;
}

// ---------------- launch ----------------
extern "C" void kernel_launch(void* const* d_in, const int* in_sizes, int n_in,
                              void* d_out, int out_size) {
    const float* x; const float* D;
    if (in_sizes[0] == DDIM*KDIM) { D = (const float*)d_in[0]; x = (const float*)d_in[1]; }
    else                          { x = (const float*)d_in[0]; D = (const float*)d_in[1]; }
    float* out = (float*)d_out;

    cudaFuncSetAttribute(prepgram_kernel, cudaFuncAttributeMaxDynamicSharedMemorySize, SMEM_DN_BYTES);
    prepgram_kernel<<<32, 256, SMEM_DN_BYTES>>>(D);
    xt_kernel<<<dim3(128, 2, 8), dim3(32, 8)>>>(x);
    cudaMemsetAsync(out + IDS_OFF, 0, (size_t)16777216 * sizeof(float));
    cudaFuncSetAttribute(alpha_kernel, cudaFuncAttributeMaxDynamicSharedMemorySize, SMEM_A_TOTAL);
    alpha_kernel<<<152, A_THREADS, SMEM_A_TOTAL>>>();
    ompsel_kernel<<<B_BLOCKS, B_THREADS>>>(out);
    outt_kernel<<<dim3(128, 2, 8), dim3(32, 8)>>>(out);
    fin_kernel<<<1, 32>>>(out);
}

// round 9
// speedup vs baseline: 1.1268x; 1.0840x over previous
#include <cuda_runtime.h>
#include <cstdint>

#define N_SIG 32768
#define KDIM  512
#define DDIM  64
#define NNZ   4
#define REGEPS 1e-7f

// Output tuple layout (flat f32):
#define OUT_OFF   0ll         // [8,64,64,64]  = 2097152
#define DIFF1_OFF 2097152ll
#define DIFF2_OFF 2097153ll
#define IDS_OFF   2097154ll   // [8,512,64,64] = 16777216
#define NSTEP_OFF 18874370ll
#define MEAND_OFF 18874371ll
#define MEANZ_OFF 18874372ll
#define NORMZ_OFF 18874373ll
#define TOPP_OFF  18874374ll
#define NZERO_OFF 18874375ll

// ---------------- scratch (no allocation allowed) ----------------
__device__ float g_Dn[DDIM*KDIM];
__device__ float g_DnT[KDIM*DDIM];
__device__ float g_G[KDIM*KDIM];
__device__ float g_xt[(size_t)N_SIG*DDIM];
__device__ float g_qt[(size_t)N_SIG*DDIM];
__device__ float g_alpha0[(size_t)N_SIG*KDIM];   // 64MB hand-off
__device__ float g_diffsum, g_zsum, g_meanDsum;
__device__ int   g_hist[5];

// ---------------- helpers ----------------
__device__ __forceinline__ unsigned long long ffma2(unsigned long long a,
                                                    unsigned long long b,
                                                    unsigned long long c) {
    unsigned long long d;
    asm("fma.rn.f32x2 %0, %1, %2, %3;" : "=l"(d) : "l"(a), "l"(b), "l"(c));
    return d;
}
__device__ __forceinline__ unsigned long long packdup(float v) {
    unsigned long long r;
    asm("mov.b64 %0, {%1, %1};" : "=l"(r) : "f"(v));
    return r;
}
__device__ __forceinline__ float sel16(const float a[16], int t) {
    float r = a[0];
    #pragma unroll
    for (int i = 1; i < 16; i++) if (t == i) r = a[i];
    return r;
}

// ---------------- fused prep + Gram ----------------
__global__ __launch_bounds__(256, 1) void prepgram_kernel(const float* __restrict__ D) {
    extern __shared__ float sd[];  // 64*512 floats = 128KB
    __shared__ float red[256];
    int t = threadIdx.x;
    for (int i = t; i < DDIM*KDIM; i += 256) sd[i] = D[i];
    __syncthreads();
    // normalize: thread t owns columns t and t+256
    float asum_loc = 0.f;
    #pragma unroll
    for (int half = 0; half < 2; half++) {
        int k = t + half*256;
        float ss = 0.f;
        #pragma unroll 8
        for (int d = 0; d < DDIM; d++) { float v = sd[d*KDIM + k]; ss += v*v; }
        float inv = 1.0f / sqrtf(ss);
        #pragma unroll 8
        for (int d = 0; d < DDIM; d++) {
            float v = sd[d*KDIM + k] * inv;
            sd[d*KDIM + k] = v;
            asum_loc += fabsf(v);
        }
    }
    __syncthreads();

    // Gram rows [r0, r0+16)
    int r0 = blockIdx.x * 16;
    #pragma unroll 1
    for (int jp = 0; jp < 2; jp++) {
        int j = t + jp*256;
        float a[16];
        #pragma unroll
        for (int r = 0; r < 16; r++) a[r] = 0.f;
        #pragma unroll 4
        for (int d = 0; d < DDIM; d++) {
            float cj = sd[d*KDIM + j];
            #pragma unroll
            for (int r = 0; r < 16; r++) a[r] += sd[d*KDIM + r0 + r] * cj;
        }
        #pragma unroll
        for (int r = 0; r < 16; r++) g_G[(size_t)(r0 + r)*KDIM + j] = a[r];
    }

    if (blockIdx.x == 0) {
        for (int i = t; i < DDIM*KDIM; i += 256) g_Dn[i] = sd[i];
        #pragma unroll
        for (int half = 0; half < 2; half++) {
            int k = t + half*256;
            #pragma unroll 8
            for (int d = 0; d < DDIM; d++) g_DnT[k*DDIM + d] = sd[d*KDIM + k];
        }
        red[t] = asum_loc; __syncthreads();
        for (int off = 128; off > 0; off >>= 1) {
            if (t < off) red[t] += red[t + off];
            __syncthreads();
        }
        if (t == 0) {
            g_meanDsum = red[0];
            g_diffsum = 0.f; g_zsum = 0.f;
        }
        if (t < 5) g_hist[t] = 0;
    }
}

// ---------------- transpose x [B,DIM,H,W] -> x_t [N,DIM] ----------------
__global__ void xt_kernel(const float* __restrict__ x) {
    __shared__ float tile[32][33];
    int b   = blockIdx.z;
    int hw0 = blockIdx.x * 32;
    int d0  = blockIdx.y * 32;
    int tx = threadIdx.x, ty = threadIdx.y;
    #pragma unroll
    for (int i = 0; i < 4; i++) {
        int d = d0 + ty + i*8;
        tile[ty + i*8][tx] = x[(size_t)(b*DDIM + d)*4096 + hw0 + tx];
    }
    __syncthreads();
    #pragma unroll
    for (int i = 0; i < 4; i++) {
        int hw = hw0 + ty + i*8;
        g_xt[(size_t)(b*4096 + hw)*DDIM + d0 + tx] = tile[tx][ty + i*8];
    }
}

// ---------------- transpose q_t [N,DIM] -> out [B,DIM,H,W] ----------------
__global__ void outt_kernel(float* __restrict__ out) {
    __shared__ float tile[32][33];
    int b   = blockIdx.z;
    int hw0 = blockIdx.x * 32;
    int d0  = blockIdx.y * 32;
    int tx = threadIdx.x, ty = threadIdx.y;
    #pragma unroll
    for (int i = 0; i < 4; i++) {
        int hw = hw0 + ty + i*8;
        tile[ty + i*8][tx] = g_qt[(size_t)(b*4096 + hw)*DDIM + d0 + tx];
    }
    __syncthreads();
    #pragma unroll
    for (int i = 0; i < 4; i++) {
        int d = d0 + ty + i*8;
        out[(size_t)(b*DDIM + d)*4096 + hw0 + tx] = tile[tx][ty + i*8];
    }
}

// ---------------- Kernel A: alpha0 = X * Dn, K-split halves, 8 sig/warp ------
// Even blocks compute k in [0,256), odd blocks k in [256,512).
// smem/CTA = 64KB (half Dn) + 32KB staging -> 2 CTAs/SM, 16 warps/SM.
#define A_THREADS 256
#define A_WARPS   8
#define A_SIG     8
#define A_NGRP    (N_SIG / A_SIG)                   // 4096
#define KHALF     256
#define SMEM_DNH_BYTES (DDIM*KHALF*4)               // 65536
#define SMEM_XH_OFF    SMEM_DNH_BYTES
#define SMEM_XH_BYTES  (A_WARPS*A_SIG*DDIM*8)      // 32768
#define SMEM_AH_TOTAL  (SMEM_XH_OFF + SMEM_XH_BYTES)  // 98304

__global__ __launch_bounds__(A_THREADS, 2)
void alpha_kernel() {
    extern __shared__ unsigned char smraw[];
    float* sDn = (float*)smraw;                       // [64][256] half-dict
    unsigned long long* sX = (unsigned long long*)(smraw + SMEM_XH_OFF);

    int tid  = threadIdx.x;
    int lane = tid & 31;
    int w    = tid >> 5;
    int khalf = blockIdx.x & 1;
    int bgrp  = blockIdx.x >> 1;

    // load this block's Dn half (columns khalf*256 .. +256)
    for (int i = tid; i < DDIM*KHALF; i += A_THREADS) {
        int d = i >> 8, j = i & 255;
        sDn[i] = g_Dn[d*KDIM + khalf*KHALF + j];
    }
    __syncthreads();

    unsigned long long* xw = sX + w * A_SIG * DDIM;
    const ulonglong2* sDn2 = (const ulonglong2*)sDn;  // 64 per d-row

    int gw = bgrp * A_WARPS + w;
    int nw = (gridDim.x >> 1) * A_WARPS;

    // prefetch first group's x into registers
    float xf[2*A_SIG];
    if (gw < A_NGRP) {
        #pragma unroll
        for (int s = 0; s < A_SIG; s++) {
            const float* xp = g_xt + (size_t)(gw*A_SIG + s) * DDIM;
            xf[2*s]     = __ldg(xp + lane);
            xf[2*s + 1] = __ldg(xp + lane + 32);
        }
    }

    #pragma unroll 1
    for (int g = gw; g < A_NGRP; g += nw) {
        __syncwarp();
        #pragma unroll
        for (int s = 0; s < A_SIG; s++) {
            xw[s*DDIM + lane]      = packdup(xf[2*s]);
            xw[s*DDIM + lane + 32] = packdup(xf[2*s + 1]);
        }
        __syncwarp();
        int g2 = g + nw;
        if (g2 < A_NGRP) {
            #pragma unroll
            for (int s = 0; s < A_SIG; s++) {
                const float* xp = g_xt + (size_t)(g2*A_SIG + s) * DDIM;
                xf[2*s]     = __ldg(xp + lane);
                xf[2*s + 1] = __ldg(xp + lane + 32);
            }
        }

        unsigned long long acc[A_SIG][4];
        #pragma unroll
        for (int s = 0; s < A_SIG; s++)
            #pragma unroll
            for (int t = 0; t < 4; t++) acc[s][t] = 0ull;

        #pragma unroll 4
        for (int d = 0; d < DDIM; d++) {
            unsigned long long xd[A_SIG];
            #pragma unroll
            for (int s = 0; s < A_SIG; s++) xd[s] = xw[s*DDIM + d];
            #pragma unroll
            for (int c2 = 0; c2 < 2; c2++) {
                ulonglong2 q = sDn2[d*64 + c2*32 + lane];
                #pragma unroll
                for (int s = 0; s < A_SIG; s++) {
                    acc[s][c2*2]     = ffma2(q.x, xd[s], acc[s][c2*2]);
                    acc[s][c2*2 + 1] = ffma2(q.y, xd[s], acc[s][c2*2 + 1]);
                }
            }
        }

        // store half-row: float k = khalf*256 + c2*128 + lane*4 (+0..3)
        #pragma unroll
        for (int s = 0; s < A_SIG; s++) {
            ulonglong2* ap = (ulonglong2*)(g_alpha0 + (size_t)(g*A_SIG + s) * KDIM);
            #pragma unroll
            for (int c2 = 0; c2 < 2; c2++) {
                ulonglong2 v; v.x = acc[s][c2*2]; v.y = acc[s][c2*2 + 1];
                ap[khalf*64 + c2*32 + lane] = v;
            }
        }
    }
}

// ---------------- Kernel B: OMP iterations, 1 signal per warp ----------------
#define B_THREADS 256
#define B_WARPS   8
#define B_BLOCKS  1024   // 8192 warps x 4 signals = 32768

__global__ __launch_bounds__(B_THREADS, 3)
void ompsel_kernel(float* __restrict__ out) {
    __shared__ float sAccF[2];
    __shared__ int   sHist[5];
    int tid  = threadIdx.x;
    int lane = tid & 31;
    int w    = tid >> 5;
    if (tid < 2) sAccF[tid] = 0.f;
    if (tid < 5) sHist[tid] = 0;
    __syncthreads();

    float diffacc = 0.f, zacc = 0.f;
    int h0 = 0, h1 = 0, h2 = 0, h3 = 0, h4 = 0;

    int gw = blockIdx.x * B_WARPS + w;
    #pragma unroll 1
    for (int s4 = 0; s4 < 4; s4++) {
        int n = gw * 4 + s4;

        // load alpha0: a0[c2*4+j] holds k = c2*128 + lane*4 + j
        const float4* ap = (const float4*)(g_alpha0 + (size_t)n * KDIM);
        float a0[16];
        #pragma unroll
        for (int c2 = 0; c2 < 4; c2++) {
            float4 q = __ldg(ap + c2*32 + lane);
            a0[c2*4 + 0] = q.x; a0[c2*4 + 1] = q.y;
            a0[c2*4 + 2] = q.z; a0[c2*4 + 3] = q.w;
        }

        int idx[4]; float gam[4]; float rhs[4]; float Ms[4][4];
        #pragma unroll
        for (int r = 0; r < 4; r++)
            #pragma unroll
            for (int c = 0; c < 4; c++) Ms[r][c] = 0.f;

        #pragma unroll
        for (int it = 0; it < NNZ; it++) {
            // alpha = alpha0 - sum_p gam[p]*G[idx[p],:]
            float vv[16];
            #pragma unroll
            for (int t = 0; t < 16; t++) vv[t] = a0[t];
            #pragma unroll
            for (int p = 0; p < NNZ - 1; p++) if (p < it) {
                const float4* Gr = (const float4*)(g_G + (size_t)idx[p]*KDIM);
                float gp = gam[p];
                #pragma unroll
                for (int c2 = 0; c2 < 4; c2++) {
                    float4 gq = __ldg(Gr + c2*32 + lane);
                    vv[c2*4 + 0] -= gp * gq.x;
                    vv[c2*4 + 1] -= gp * gq.y;
                    vv[c2*4 + 2] -= gp * gq.z;
                    vv[c2*4 + 3] -= gp * gq.w;
                }
            }
            // argmax |alpha| (first-index tie-break)
            float bv = -1.f; int bk = 0;
            #pragma unroll
            for (int t = 0; t < 16; t++) {
                int k = ((t >> 2) << 7) | (lane << 2) | (t & 3);
                float av = fabsf(vv[t]);
                if (av > bv) { bv = av; bk = k; }
            }
            #pragma unroll
            for (int off = 16; off > 0; off >>= 1) {
                float ov = __shfl_xor_sync(0xffffffffu, bv, off);
                int   ok = __shfl_xor_sync(0xffffffffu, bk, off);
                if (ov > bv || (ov == bv && ok < bk)) { bv = ov; bk = ok; }
            }
            idx[it] = bk;
            // rhs[it] = alpha0[bk]
            int tt = (((bk >> 7) & 3) << 2) | (bk & 3);
            float myv = sel16(a0, tt);
            rhs[it] = __shfl_sync(0xffffffffu, myv, (bk >> 2) & 31);
            // extend G_sub
            #pragma unroll
            for (int b2 = 0; b2 < NNZ; b2++) if (b2 <= it) {
                float gv = __ldg(g_G + (size_t)bk*KDIM + idx[b2]);
                Ms[it][b2] = gv; Ms[b2][it] = gv;
            }
            // solve (it+1)x(it+1) SPD system (G_sub + eps*I) gamma = rhs
            {
                float M[4][4], yv[4], gv2[4];
                #pragma unroll
                for (int r = 0; r < 4; r++) {
                    #pragma unroll
                    for (int c = 0; c < 4; c++) M[r][c] = Ms[r][c];
                    M[r][r] += REGEPS;
                    yv[r] = rhs[r];
                    gv2[r] = 0.f;
                }
                #pragma unroll
                for (int c = 0; c < 4; c++) if (c <= it) {
                    float pinv = 1.f / M[c][c];
                    #pragma unroll
                    for (int r = 0; r < 4; r++) if (r > c && r <= it) {
                        float f = M[r][c] * pinv;
                        #pragma unroll
                        for (int cc = 0; cc < 4; cc++) if (cc >= c && cc <= it)
                            M[r][cc] -= f * M[c][cc];
                        yv[r] -= f * yv[c];
                    }
                }
                #pragma unroll
                for (int r = 3; r >= 0; r--) if (r <= it) {
                    float a2 = yv[r];
                    #pragma unroll
                    for (int cc = 0; cc < 4; cc++) if (cc > r && cc <= it)
                        a2 -= M[r][cc] * gv2[cc];
                    gv2[r] = a2 / M[r][r];
                }
                #pragma unroll
                for (int r = 0; r < 4; r++) if (r <= it) gam[r] = gv2[r];
            }
        }

        // duplicate handling: final cell value = gamma of LAST occurrence
        bool lastocc[4];
        #pragma unroll
        for (int a = 0; a < 4; a++) {
            bool lo2 = true;
            #pragma unroll
            for (int b2 = a + 1; b2 < 4; b2++) if (idx[b2] == idx[a]) lo2 = false;
            lastocc[a] = lo2;
        }

        // quant = code @ Dn^T (DnT rows L2-resident)
        float q0 = 0.f, q1 = 0.f;
        #pragma unroll
        for (int a = 0; a < 4; a++) if (lastocc[a]) {
            const float* dt = g_DnT + (size_t)idx[a]*DDIM;
            q0 += gam[a] * __ldg(dt + lane);
            q1 += gam[a] * __ldg(dt + lane + 32);
        }
        g_qt[(size_t)n*DDIM + lane]      = q0;
        g_qt[(size_t)n*DDIM + lane + 32] = q1;
        const float* xp = g_xt + (size_t)n * DDIM;
        float xv0 = __ldg(xp + lane);
        float xv1 = __ldg(xp + lane + 32);
        diffacc += (q0 - xv0)*(q0 - xv0) + (q1 - xv1)*(q1 - xv1);

        if (lane == 0) {
            int b = n >> 12, hw = n & 4095;
            float* ids = out + IDS_OFF + (size_t)b*(KDIM*4096) + hw;
            int cnt = 0;
            #pragma unroll
            for (int a = 0; a < 4; a++) {
                ids[(size_t)idx[a]*4096] = gam[a];  // program order: last write wins
                if (lastocc[a] && gam[a] != 0.f) { cnt++; zacc += fabsf(gam[a]); }
            }
            if (cnt == 0) h0++; else if (cnt == 1) h1++; else if (cnt == 2) h2++;
            else if (cnt == 3) h3++; else h4++;
        }
    }

    // ---- reductions ----
    #pragma unroll
    for (int off = 16; off > 0; off >>= 1) {
        diffacc += __shfl_xor_sync(0xffffffffu, diffacc, off);
        zacc    += __shfl_xor_sync(0xffffffffu, zacc, off);
    }
    if (lane == 0) {
        atomicAdd(&sAccF[0], diffacc);
        atomicAdd(&sAccF[1], zacc);
        if (h0) atomicAdd(&sHist[0], h0);
        if (h1) atomicAdd(&sHist[1], h1);
        if (h2) atomicAdd(&sHist[2], h2);
        if (h3) atomicAdd(&sHist[3], h3);
        if (h4) atomicAdd(&sHist[4], h4);
    }
    __syncthreads();
    if (tid == 0) {
        atomicAdd(&g_diffsum, sAccF[0]);
        atomicAdd(&g_zsum, sAccF[1]);
    }
    if (tid < 5) { int v = sHist[tid]; if (v) atomicAdd(&g_hist[tid], v); }
}

// ---------------- finalize scalars ----------------
__global__ void fin_kernel(float* __restrict__ out) {
    if (threadIdx.x != 0) return;
    float diff = g_diffsum / 2097152.0f;
    out[DIFF1_OFF] = diff;
    out[DIFF2_OFF] = diff;
    out[NSTEP_OFF] = 4.0f;
    out[MEAND_OFF] = g_meanDsum / 32768.0f;
    out[MEANZ_OFF] = g_zsum / 16777216.0f;
    int c0 = g_hist[0], c1 = g_hist[1], c2 = g_hist[2], c3 = g_hist[3], c4 = g_hist[4];
    float sumw = 1.f*c1 + 2.f*c2 + 3.f*c3 + 4.f*c4;
    out[NORMZ_OFF] = sumw / 32768.0f;
    const int topk = 327;  // int(32768 * 0.01)
    int cum = c4; float tp = 4.f;
    if (cum < topk) { cum += c3; tp = 3.f; }
    if (cum < topk) { cum += c2; tp = 2.f; }
    if (cum < topk) { cum += c1; tp = 1.f; }
    if (cum < topk) { tp = 0.f; }
    out[TOPP_OFF]  = tp;
    out[NZERO_OFF] = (float)c0;
}

// ---------------- launch ----------------
extern "C" void kernel_launch(void* const* d_in, const int* in_sizes, int n_in,
                              void* d_out, int out_size) {
    const float* x; const float* D;
    if (in_sizes[0] == DDIM*KDIM) { D = (const float*)d_in[0]; x = (const float*)d_in[1]; }
    else                          { x = (const float*)d_in[0]; D = (const float*)d_in[1]; }
    float* out = (float*)d_out;

    cudaFuncSetAttribute(prepgram_kernel, cudaFuncAttributeMaxDynamicSharedMemorySize, DDIM*KDIM*4);
    prepgram_kernel<<<32, 256, DDIM*KDIM*4>>>(D);
    xt_kernel<<<dim3(128, 2, 8), dim3(32, 8)>>>(x);
    cudaMemsetAsync(out + IDS_OFF, 0, (size_t)16777216 * sizeof(float));
    cudaFuncSetAttribute(alpha_kernel, cudaFuncAttributeMaxDynamicSharedMemorySize, SMEM_AH_TOTAL);
    alpha_kernel<<<304, A_THREADS, SMEM_AH_TOTAL>>>();
    ompsel_kernel<<<B_BLOCKS, B_THREADS>>>(out);
    outt_kernel<<<dim3(128, 2, 8), dim3(32, 8)>>>(out);
    fin_kernel<<<1, 32>>>(out);
}

// round 10
// speedup vs baseline: 1.1390x; 1.0108x over previous
#include <cuda_runtime.h>
#include <cstdint>

#define N_SIG 32768
#define KDIM  512
#define DDIM  64
#define NNZ   4
#define REGEPS 1e-7f

// Output tuple layout (flat f32):
#define OUT_OFF   0ll         // [8,64,64,64]  = 2097152
#define DIFF1_OFF 2097152ll
#define DIFF2_OFF 2097153ll
#define IDS_OFF   2097154ll   // [8,512,64,64] = 16777216
#define NSTEP_OFF 18874370ll
#define MEAND_OFF 18874371ll
#define MEANZ_OFF 18874372ll
#define NORMZ_OFF 18874373ll
#define TOPP_OFF  18874374ll
#define NZERO_OFF 18874375ll

// ---------------- scratch (no allocation allowed) ----------------
__device__ float g_Dn[DDIM*KDIM];
__device__ float g_DnT[KDIM*DDIM];
__device__ float g_G[KDIM*KDIM];
__device__ float g_xt[(size_t)N_SIG*DDIM];
__device__ float g_qt[(size_t)N_SIG*DDIM];
__device__ float g_alpha0[(size_t)N_SIG*KDIM];   // 64MB hand-off
__device__ float g_diffsum, g_zsum, g_meanDsum;
__device__ int   g_hist[5];

// ---------------- helpers ----------------
__device__ __forceinline__ unsigned long long ffma2(unsigned long long a,
                                                    unsigned long long b,
                                                    unsigned long long c) {
    unsigned long long d;
    asm("fma.rn.f32x2 %0, %1, %2, %3;" : "=l"(d) : "l"(a), "l"(b), "l"(c));
    return d;
}
__device__ __forceinline__ unsigned long long packdup(float v) {
    unsigned long long r;
    asm("mov.b64 %0, {%1, %1};" : "=l"(r) : "f"(v));
    return r;
}
__device__ __forceinline__ float sel16(const float a[16], int t) {
    float r = a[0];
    #pragma unroll
    for (int i = 1; i < 16; i++) if (t == i) r = a[i];
    return r;
}

// ---------------- fused prep + Gram ----------------
__global__ __launch_bounds__(256, 1) void prepgram_kernel(const float* __restrict__ D) {
    extern __shared__ float sd[];  // 64*512 floats = 128KB
    __shared__ float red[256];
    int t = threadIdx.x;
    for (int i = t; i < DDIM*KDIM; i += 256) sd[i] = D[i];
    __syncthreads();
    // normalize: thread t owns columns t and t+256
    float asum_loc = 0.f;
    #pragma unroll
    for (int half = 0; half < 2; half++) {
        int k = t + half*256;
        float ss = 0.f;
        #pragma unroll 8
        for (int d = 0; d < DDIM; d++) { float v = sd[d*KDIM + k]; ss += v*v; }
        float inv = 1.0f / sqrtf(ss);
        #pragma unroll 8
        for (int d = 0; d < DDIM; d++) {
            float v = sd[d*KDIM + k] * inv;
            sd[d*KDIM + k] = v;
            asum_loc += fabsf(v);
        }
    }
    __syncthreads();

    // Gram rows [r0, r0+16)
    int r0 = blockIdx.x * 16;
    #pragma unroll 1
    for (int jp = 0; jp < 2; jp++) {
        int j = t + jp*256;
        float a[16];
        #pragma unroll
        for (int r = 0; r < 16; r++) a[r] = 0.f;
        #pragma unroll 4
        for (int d = 0; d < DDIM; d++) {
            float cj = sd[d*KDIM + j];
            #pragma unroll
            for (int r = 0; r < 16; r++) a[r] += sd[d*KDIM + r0 + r] * cj;
        }
        #pragma unroll
        for (int r = 0; r < 16; r++) g_G[(size_t)(r0 + r)*KDIM + j] = a[r];
    }

    if (blockIdx.x == 0) {
        for (int i = t; i < DDIM*KDIM; i += 256) g_Dn[i] = sd[i];
        #pragma unroll
        for (int half = 0; half < 2; half++) {
            int k = t + half*256;
            #pragma unroll 8
            for (int d = 0; d < DDIM; d++) g_DnT[k*DDIM + d] = sd[d*KDIM + k];
        }
        red[t] = asum_loc; __syncthreads();
        for (int off = 128; off > 0; off >>= 1) {
            if (t < off) red[t] += red[t + off];
            __syncthreads();
        }
        if (t == 0) {
            g_meanDsum = red[0];
            g_diffsum = 0.f; g_zsum = 0.f;
        }
        if (t < 5) g_hist[t] = 0;
    }
}

// ---------------- transpose x [B,DIM,H,W] -> x_t [N,DIM] ----------------
__global__ void xt_kernel(const float* __restrict__ x) {
    __shared__ float tile[32][33];
    int b   = blockIdx.z;
    int hw0 = blockIdx.x * 32;
    int d0  = blockIdx.y * 32;
    int tx = threadIdx.x, ty = threadIdx.y;
    #pragma unroll
    for (int i = 0; i < 4; i++) {
        int d = d0 + ty + i*8;
        tile[ty + i*8][tx] = x[(size_t)(b*DDIM + d)*4096 + hw0 + tx];
    }
    __syncthreads();
    #pragma unroll
    for (int i = 0; i < 4; i++) {
        int hw = hw0 + ty + i*8;
        g_xt[(size_t)(b*4096 + hw)*DDIM + d0 + tx] = tile[tx][ty + i*8];
    }
}

// ---------------- transpose q_t [N,DIM] -> out [B,DIM,H,W] ----------------
__global__ void outt_kernel(float* __restrict__ out) {
    __shared__ float tile[32][33];
    int b   = blockIdx.z;
    int hw0 = blockIdx.x * 32;
    int d0  = blockIdx.y * 32;
    int tx = threadIdx.x, ty = threadIdx.y;
    #pragma unroll
    for (int i = 0; i < 4; i++) {
        int hw = hw0 + ty + i*8;
        tile[ty + i*8][tx] = g_qt[(size_t)(b*4096 + hw)*DDIM + d0 + tx];
    }
    __syncthreads();
    #pragma unroll
    for (int i = 0; i < 4; i++) {
        int d = d0 + ty + i*8;
        out[(size_t)(b*DDIM + d)*4096 + hw0 + tx] = tile[tx][ty + i*8];
    }
}

// ---------------- Kernel A: alpha0 = X * Dn, K-split halves, 8 sig/warp ------
// Even blocks compute k in [0,256), odd blocks k in [256,512).
// smem/CTA = 64KB (half Dn) + 32KB staging -> 2 CTAs/SM, 16 warps/SM.
#define A_THREADS 256
#define A_WARPS   8
#define A_SIG     8
#define A_NGRP    (N_SIG / A_SIG)                   // 4096
#define KHALF     256
#define SMEM_DNH_BYTES (DDIM*KHALF*4)               // 65536
#define SMEM_XH_OFF    SMEM_DNH_BYTES
#define SMEM_XH_BYTES  (A_WARPS*A_SIG*DDIM*8)      // 32768
#define SMEM_AH_TOTAL  (SMEM_XH_OFF + SMEM_XH_BYTES)  // 98304

__global__ __launch_bounds__(A_THREADS, 2)
void alpha_kernel() {
    extern __shared__ unsigned char smraw[];
    float* sDn = (float*)smraw;                       // [64][256] half-dict
    unsigned long long* sX = (unsigned long long*)(smraw + SMEM_XH_OFF);

    int tid  = threadIdx.x;
    int lane = tid & 31;
    int w    = tid >> 5;
    int khalf = blockIdx.x & 1;
    int bgrp  = blockIdx.x >> 1;

    // load this block's Dn half (columns khalf*256 .. +256)
    for (int i = tid; i < DDIM*KHALF; i += A_THREADS) {
        int d = i >> 8, j = i & 255;
        sDn[i] = g_Dn[d*KDIM + khalf*KHALF + j];
    }
    __syncthreads();

    unsigned long long* xw = sX + w * A_SIG * DDIM;
    const ulonglong2* sDn2 = (const ulonglong2*)sDn;  // 64 per d-row

    int gw = bgrp * A_WARPS + w;
    int nw = (gridDim.x >> 1) * A_WARPS;

    // prefetch first group's x into registers
    float xf[2*A_SIG];
    if (gw < A_NGRP) {
        #pragma unroll
        for (int s = 0; s < A_SIG; s++) {
            const float* xp = g_xt + (size_t)(gw*A_SIG + s) * DDIM;
            xf[2*s]     = __ldg(xp + lane);
            xf[2*s + 1] = __ldg(xp + lane + 32);
        }
    }

    #pragma unroll 1
    for (int g = gw; g < A_NGRP; g += nw) {
        __syncwarp();
        #pragma unroll
        for (int s = 0; s < A_SIG; s++) {
            xw[s*DDIM + lane]      = packdup(xf[2*s]);
            xw[s*DDIM + lane + 32] = packdup(xf[2*s + 1]);
        }
        __syncwarp();
        int g2 = g + nw;
        if (g2 < A_NGRP) {
            #pragma unroll
            for (int s = 0; s < A_SIG; s++) {
                const float* xp = g_xt + (size_t)(g2*A_SIG + s) * DDIM;
                xf[2*s]     = __ldg(xp + lane);
                xf[2*s + 1] = __ldg(xp + lane + 32);
            }
        }

        unsigned long long acc[A_SIG][4];
        #pragma unroll
        for (int s = 0; s < A_SIG; s++)
            #pragma unroll
            for (int t = 0; t < 4; t++) acc[s][t] = 0ull;

        #pragma unroll 4
        for (int d = 0; d < DDIM; d++) {
            unsigned long long xd[A_SIG];
            #pragma unroll
            for (int s = 0; s < A_SIG; s++) xd[s] = xw[s*DDIM + d];
            #pragma unroll
            for (int c2 = 0; c2 < 2; c2++) {
                ulonglong2 q = sDn2[d*64 + c2*32 + lane];
                #pragma unroll
                for (int s = 0; s < A_SIG; s++) {
                    acc[s][c2*2]     = ffma2(q.x, xd[s], acc[s][c2*2]);
                    acc[s][c2*2 + 1] = ffma2(q.y, xd[s], acc[s][c2*2 + 1]);
                }
            }
        }

        // store half-row: float k = khalf*256 + c2*128 + lane*4 (+0..3)
        #pragma unroll
        for (int s = 0; s < A_SIG; s++) {
            ulonglong2* ap = (ulonglong2*)(g_alpha0 + (size_t)(g*A_SIG + s) * KDIM);
            #pragma unroll
            for (int c2 = 0; c2 < 2; c2++) {
                ulonglong2 v; v.x = acc[s][c2*2]; v.y = acc[s][c2*2 + 1];
                ap[khalf*64 + c2*32 + lane] = v;
            }
        }
    }
}

// ---------------- Kernel B: OMP iterations, 1 signal per warp ----------------
#define B_THREADS 256
#define B_WARPS   8
#define B_BLOCKS  1024   // 8192 warps x 4 signals = 32768

__global__ __launch_bounds__(B_THREADS, 3)
void ompsel_kernel(float* __restrict__ out) {
    __shared__ float sAccF[2];
    __shared__ int   sHist[5];
    int tid  = threadIdx.x;
    int lane = tid & 31;
    int w    = tid >> 5;
    if (tid < 2) sAccF[tid] = 0.f;
    if (tid < 5) sHist[tid] = 0;
    __syncthreads();

    float diffacc = 0.f, zacc = 0.f;
    int h0 = 0, h1 = 0, h2 = 0, h3 = 0, h4 = 0;

    int gw = blockIdx.x * B_WARPS + w;
    #pragma unroll 1
    for (int s4 = 0; s4 < 4; s4++) {
        int n = gw * 4 + s4;

        // load alpha0: a0[c2*4+j] holds k = c2*128 + lane*4 + j
        const float4* ap = (const float4*)(g_alpha0 + (size_t)n * KDIM);
        float a0[16];
        #pragma unroll
        for (int c2 = 0; c2 < 4; c2++) {
            float4 q = __ldg(ap + c2*32 + lane);
            a0[c2*4 + 0] = q.x; a0[c2*4 + 1] = q.y;
            a0[c2*4 + 2] = q.z; a0[c2*4 + 3] = q.w;
        }

        int idx[4]; float gam[4]; float rhs[4]; float Ms[4][4];
        #pragma unroll
        for (int r = 0; r < 4; r++)
            #pragma unroll
            for (int c = 0; c < 4; c++) Ms[r][c] = 0.f;

        #pragma unroll
        for (int it = 0; it < NNZ; it++) {
            // alpha = alpha0 - sum_p gam[p]*G[idx[p],:]
            float vv[16];
            #pragma unroll
            for (int t = 0; t < 16; t++) vv[t] = a0[t];
            #pragma unroll
            for (int p = 0; p < NNZ - 1; p++) if (p < it) {
                const float4* Gr = (const float4*)(g_G + (size_t)idx[p]*KDIM);
                float gp = gam[p];
                #pragma unroll
                for (int c2 = 0; c2 < 4; c2++) {
                    float4 gq = __ldg(Gr + c2*32 + lane);
                    vv[c2*4 + 0] -= gp * gq.x;
                    vv[c2*4 + 1] -= gp * gq.y;
                    vv[c2*4 + 2] -= gp * gq.z;
                    vv[c2*4 + 3] -= gp * gq.w;
                }
            }
            // argmax |alpha| (first-index tie-break)
            float bv = -1.f; int bk = 0;
            #pragma unroll
            for (int t = 0; t < 16; t++) {
                int k = ((t >> 2) << 7) | (lane << 2) | (t & 3);
                float av = fabsf(vv[t]);
                if (av > bv) { bv = av; bk = k; }
            }
            #pragma unroll
            for (int off = 16; off > 0; off >>= 1) {
                float ov = __shfl_xor_sync(0xffffffffu, bv, off);
                int   ok = __shfl_xor_sync(0xffffffffu, bk, off);
                if (ov > bv || (ov == bv && ok < bk)) { bv = ov; bk = ok; }
            }
            idx[it] = bk;
            // rhs[it] = alpha0[bk]
            int tt = (((bk >> 7) & 3) << 2) | (bk & 3);
            float myv = sel16(a0, tt);
            rhs[it] = __shfl_sync(0xffffffffu, myv, (bk >> 2) & 31);
            // extend G_sub
            #pragma unroll
            for (int b2 = 0; b2 < NNZ; b2++) if (b2 <= it) {
                float gv = __ldg(g_G + (size_t)bk*KDIM + idx[b2]);
                Ms[it][b2] = gv; Ms[b2][it] = gv;
            }
            // solve (it+1)x(it+1) SPD system (G_sub + eps*I) gamma = rhs
            {
                float M[4][4], yv[4], gv2[4];
                #pragma unroll
                for (int r = 0; r < 4; r++) {
                    #pragma unroll
                    for (int c = 0; c < 4; c++) M[r][c] = Ms[r][c];
                    M[r][r] += REGEPS;
                    yv[r] = rhs[r];
                    gv2[r] = 0.f;
                }
                #pragma unroll
                for (int c = 0; c < 4; c++) if (c <= it) {
                    float pinv = 1.f / M[c][c];
                    #pragma unroll
                    for (int r = 0; r < 4; r++) if (r > c && r <= it) {
                        float f = M[r][c] * pinv;
                        #pragma unroll
                        for (int cc = 0; cc < 4; cc++) if (cc >= c && cc <= it)
                            M[r][cc] -= f * M[c][cc];
                        yv[r] -= f * yv[c];
                    }
                }
                #pragma unroll
                for (int r = 3; r >= 0; r--) if (r <= it) {
                    float a2 = yv[r];
                    #pragma unroll
                    for (int cc = 0; cc < 4; cc++) if (cc > r && cc <= it)
                        a2 -= M[r][cc] * gv2[cc];
                    gv2[r] = a2 / M[r][r];
                }
                #pragma unroll
                for (int r = 0; r < 4; r++) if (r <= it) gam[r] = gv2[r];
            }
        }

        // duplicate handling: final cell value = gamma of LAST occurrence
        bool lastocc[4];
        #pragma unroll
        for (int a = 0; a < 4; a++) {
            bool lo2 = true;
            #pragma unroll
            for (int b2 = a + 1; b2 < 4; b2++) if (idx[b2] == idx[a]) lo2 = false;
            lastocc[a] = lo2;
        }

        // quant = code @ Dn^T (DnT rows L2-resident)
        float q0 = 0.f, q1 = 0.f;
        #pragma unroll
        for (int a = 0; a < 4; a++) if (lastocc[a]) {
            const float* dt = g_DnT + (size_t)idx[a]*DDIM;
            q0 += gam[a] * __ldg(dt + lane);
            q1 += gam[a] * __ldg(dt + lane + 32);
        }
        g_qt[(size_t)n*DDIM + lane]      = q0;
        g_qt[(size_t)n*DDIM + lane + 32] = q1;
        const float* xp = g_xt + (size_t)n * DDIM;
        float xv0 = __ldg(xp + lane);
        float xv1 = __ldg(xp + lane + 32);
        diffacc += (q0 - xv0)*(q0 - xv0) + (q1 - xv1)*(q1 - xv1);

        if (lane == 0) {
            int b = n >> 12, hw = n & 4095;
            float* ids = out + IDS_OFF + (size_t)b*(KDIM*4096) + hw;
            int cnt = 0;
            #pragma unroll
            for (int a = 0; a < 4; a++) {
                ids[(size_t)idx[a]*4096] = gam[a];  // program order: last write wins
                if (lastocc[a] && gam[a] != 0.f) { cnt++; zacc += fabsf(gam[a]); }
            }
            if (cnt == 0) h0++; else if (cnt == 1) h1++; else if (cnt == 2) h2++;
            else if (cnt == 3) h3++; else h4++;
        }
    }

    // ---- reductions ----
    #pragma unroll
    for (int off = 16; off > 0; off >>= 1) {
        diffacc += __shfl_xor_sync(0xffffffffu, diffacc, off);
        zacc    += __shfl_xor_sync(0xffffffffu, zacc, off);
    }
    if (lane == 0) {
        atomicAdd(&sAccF[0], diffacc);
        atomicAdd(&sAccF[1], zacc);
        if (h0) atomicAdd(&sHist[0], h0);
        if (h1) atomicAdd(&sHist[1], h1);
        if (h2) atomicAdd(&sHist[2], h2);
        if (h3) atomicAdd(&sHist[3], h3);
        if (h4) atomicAdd(&sHist[4], h4);
    }
    __syncthreads();
    if (tid == 0) {
        atomicAdd(&g_diffsum, sAccF[0]);
        atomicAdd(&g_zsum, sAccF[1]);
    }
    if (tid < 5) { int v = sHist[tid]; if (v) atomicAdd(&g_hist[tid], v); }
}

// ---------------- finalize scalars ----------------
__global__ void fin_kernel(float* __restrict__ out) {
    if (threadIdx.x != 0) return;
    float diff = g_diffsum / 2097152.0f;
    out[DIFF1_OFF] = diff;
    out[DIFF2_OFF] = diff;
    out[NSTEP_OFF] = 4.0f;
    out[MEAND_OFF] = g_meanDsum / 32768.0f;
    out[MEANZ_OFF] = g_zsum / 16777216.0f;
    int c0 = g_hist[0], c1 = g_hist[1], c2 = g_hist[2], c3 = g_hist[3], c4 = g_hist[4];
    float sumw = 1.f*c1 + 2.f*c2 + 3.f*c3 + 4.f*c4;
    out[NORMZ_OFF] = sumw / 32768.0f;
    const int topk = 327;  // int(32768 * 0.01)
    int cum = c4; float tp = 4.f;
    if (cum < topk) { cum += c3; tp = 3.f; }
    if (cum < topk) { cum += c2; tp = 2.f; }
    if (cum < topk) { cum += c1; tp = 1.f; }
    if (cum < topk) { tp = 0.f; }
    out[TOPP_OFF]  = tp;
    out[NZERO_OFF] = (float)c0;
}

// ---------------- launch ----------------
extern "C" void kernel_launch(void* const* d_in, const int* in_sizes, int n_in,
                              void* d_out, int out_size) {
    const float* x; const float* D;
    if (in_sizes[0] == DDIM*KDIM) { D = (const float*)d_in[0]; x = (const float*)d_in[1]; }
    else                          { x = (const float*)d_in[0]; D = (const float*)d_in[1]; }
    float* out = (float*)d_out;

    cudaFuncSetAttribute(prepgram_kernel, cudaFuncAttributeMaxDynamicSharedMemorySize, DDIM*KDIM*4);
    prepgram_kernel<<<32, 256, DDIM*KDIM*4>>>(D);
    xt_kernel<<<dim3(128, 2, 8), dim3(32, 8)>>>(x);
    cudaMemsetAsync(out + IDS_OFF, 0, (size_t)16777216 * sizeof(float));
    cudaFuncSetAttribute(alpha_kernel, cudaFuncAttributeMaxDynamicSharedMemorySize, SMEM_AH_TOTAL);
    alpha_kernel<<<304, A_THREADS, SMEM_AH_TOTAL>>>();
    ompsel_kernel<<<B_BLOCKS, B_THREADS>>>(out);
    outt_kernel<<<dim3(128, 2, 8), dim3(32, 8)>>>(out);
    fin_kernel<<<1, 32>>>(out);
}

// round 13
// speedup vs baseline: 1.1914x; 1.0460x over previous
#include <cuda_runtime.h>
#include <cstdint>

#define N_SIG 32768
#define KDIM  512
#define DDIM  64
#define NNZ   4
#define REGEPS 1e-7f

#define OUT_OFF   0ll
#define DIFF1_OFF 2097152ll
#define DIFF2_OFF 2097153ll
#define IDS_OFF   2097154ll
#define NSTEP_OFF 18874370ll
#define MEAND_OFF 18874371ll
#define MEANZ_OFF 18874372ll
#define NORMZ_OFF 18874373ll
#define TOPP_OFF  18874374ll
#define NZERO_OFF 18874375ll

__device__ float g_Dn[DDIM*KDIM];
__device__ float g_DnT[KDIM*DDIM];
__device__ float g_G[KDIM*KDIM];
__device__ float g_xt[(size_t)N_SIG*DDIM];
__device__ float g_qt[(size_t)N_SIG*DDIM];
__device__ float g_alpha0[(size_t)N_SIG*KDIM];
__device__ float g_diffsum, g_zsum, g_meanDsum;
__device__ int   g_hist[5];

__device__ __forceinline__ unsigned long long ffma2(unsigned long long a,
                                                    unsigned long long b,
                                                    unsigned long long c) {
    unsigned long long d;
    asm("fma.rn.f32x2 %0, %1, %2, %3;" : "=l"(d) : "l"(a), "l"(b), "l"(c));
    return d;
}
__device__ __forceinline__ unsigned long long packdup(float v) {
    unsigned long long r;
    asm("mov.b64 %0, {%1, %1};" : "=l"(r) : "f"(v));
    return r;
}
__device__ __forceinline__ float sel16(const float a[16], int t) {
    float r = a[0];
    #pragma unroll
    for (int i = 1; i < 16; i++) if (t == i) r = a[i];
    return r;
}

// ---------------- fused prep + Gram ----------------
__global__ __launch_bounds__(256, 1) void prepgram_kernel(const float* __restrict__ D) {
    extern __shared__ float sd[];  // 128KB
    __shared__ float red[256];
    int t = threadIdx.x;
    for (int i = t; i < DDIM*KDIM; i += 256) sd[i] = D[i];
    __syncthreads();
    float asum_loc = 0.f;
    #pragma unroll
    for (int half = 0; half < 2; half++) {
        int k = t + half*256;
        float ss = 0.f;
        #pragma unroll 8
        for (int d = 0; d < DDIM; d++) { float v = sd[d*KDIM + k]; ss += v*v; }
        float inv = 1.0f / sqrtf(ss);
        #pragma unroll 8
        for (int d = 0; d < DDIM; d++) {
            float v = sd[d*KDIM + k] * inv;
            sd[d*KDIM + k] = v;
            asum_loc += fabsf(v);
        }
    }
    __syncthreads();
    int r0 = blockIdx.x * 16;
    #pragma unroll 1
    for (int jp = 0; jp < 2; jp++) {
        int j = t + jp*256;
        float a[16];
        #pragma unroll
        for (int r = 0; r < 16; r++) a[r] = 0.f;
        #pragma unroll 4
        for (int d = 0; d < DDIM; d++) {
            float cj = sd[d*KDIM + j];
            #pragma unroll
            for (int r = 0; r < 16; r++) a[r] += sd[d*KDIM + r0 + r] * cj;
        }
        #pragma unroll
        for (int r = 0; r < 16; r++) g_G[(size_t)(r0 + r)*KDIM + j] = a[r];
    }
    if (blockIdx.x == 0) {
        for (int i = t; i < DDIM*KDIM; i += 256) g_Dn[i] = sd[i];
        #pragma unroll
        for (int half = 0; half < 2; half++) {
            int k = t + half*256;
            #pragma unroll 8
            for (int d = 0; d < DDIM; d++) g_DnT[k*DDIM + d] = sd[d*KDIM + k];
        }
        red[t] = asum_loc; __syncthreads();
        for (int off = 128; off > 0; off >>= 1) {
            if (t < off) red[t] += red[t + off];
            __syncthreads();
        }
        if (t == 0) { g_meanDsum = red[0]; g_diffsum = 0.f; g_zsum = 0.f; }
        if (t < 5) g_hist[t] = 0;
    }
}

// ---------------- transpose x [B,DIM,H,W] -> x_t [N,DIM] ----------------
__global__ void xt_kernel(const float* __restrict__ x) {
    __shared__ float tile[32][33];
    int b   = blockIdx.z;
    int hw0 = blockIdx.x * 32;
    int d0  = blockIdx.y * 32;
    int tx = threadIdx.x, ty = threadIdx.y;
    #pragma unroll
    for (int i = 0; i < 4; i++) {
        int d = d0 + ty + i*8;
        tile[ty + i*8][tx] = x[(size_t)(b*DDIM + d)*4096 + hw0 + tx];
    }
    __syncthreads();
    #pragma unroll
    for (int i = 0; i < 4; i++) {
        int hw = hw0 + ty + i*8;
        g_xt[(size_t)(b*4096 + hw)*DDIM + d0 + tx] = tile[tx][ty + i*8];
    }
}

// ---------------- transpose q_t [N,DIM] -> out [B,DIM,H,W] ----------------
__global__ void outt_kernel(float* __restrict__ out) {
    __shared__ float tile[32][33];
    int b   = blockIdx.z;
    int hw0 = blockIdx.x * 32;
    int d0  = blockIdx.y * 32;
    int tx = threadIdx.x, ty = threadIdx.y;
    #pragma unroll
    for (int i = 0; i < 4; i++) {
        int hw = hw0 + ty + i*8;
        tile[ty + i*8][tx] = g_qt[(size_t)(b*4096 + hw)*DDIM + d0 + tx];
    }
    __syncthreads();
    #pragma unroll
    for (int i = 0; i < 4; i++) {
        int d = d0 + ty + i*8;
        out[(size_t)(b*DDIM + d)*4096 + hw0 + tx] = tile[tx][ty + i*8];
    }
}

// ---- Kernel A: alpha0 = X * Dn, K-quarter split, 8 sig/warp, 3 CTAs/SM ----
// blockIdx&3 selects dict cols [kq*128, kq*128+128). smem = 32KB dict + 16KB x.
#define A_THREADS 256
#define A_WARPS   8
#define A_SIG     8
#define A_NGRP    (N_SIG / A_SIG)                   // 4096
#define KQ        128
#define SMEM_DNQ_BYTES (DDIM*KQ*4)                  // 32768
#define SMEM_XQ_OFF    SMEM_DNQ_BYTES
#define SMEM_XQ_BYTES  (A_WARPS*A_SIG*DDIM*4)      // 16384
#define SMEM_AQ_TOTAL  (SMEM_XQ_OFF + SMEM_XQ_BYTES)  // 49152

__global__ __launch_bounds__(A_THREADS, 3)
void alpha_kernel() {
    extern __shared__ unsigned char smraw[];
    float* sDn = (float*)smraw;                 // [64][128] quarter-dict
    float* sX  = (float*)(smraw + SMEM_XQ_OFF);

    int tid  = threadIdx.x;
    int lane = tid & 31;
    int w    = tid >> 5;
    int kq   = blockIdx.x & 3;
    int bgrp = blockIdx.x >> 2;

    for (int i = tid; i < DDIM*KQ; i += A_THREADS) {
        int d = i >> 7, j = i & 127;
        sDn[i] = g_Dn[d*KDIM + kq*KQ + j];
    }
    __syncthreads();

    float* xw = sX + w * A_SIG * DDIM;
    const ulonglong2* sDn2 = (const ulonglong2*)sDn;   // 32 per d-row

    int gw = bgrp * A_WARPS + w;
    int nw = (gridDim.x >> 2) * A_WARPS;

    float xf[2*A_SIG];
    if (gw < A_NGRP) {
        #pragma unroll
        for (int s = 0; s < A_SIG; s++) {
            const float* xp = g_xt + (size_t)(gw*A_SIG + s) * DDIM;
            xf[2*s]     = __ldg(xp + lane);
            xf[2*s + 1] = __ldg(xp + lane + 32);
        }
    }

    #pragma unroll 1
    for (int g = gw; g < A_NGRP; g += nw) {
        __syncwarp();
        #pragma unroll
        for (int s = 0; s < A_SIG; s++) {
            xw[s*DDIM + lane]      = xf[2*s];
            xw[s*DDIM + lane + 32] = xf[2*s + 1];
        }
        __syncwarp();
        int g2 = g + nw;
        if (g2 < A_NGRP) {
            #pragma unroll
            for (int s = 0; s < A_SIG; s++) {
                const float* xp = g_xt + (size_t)(g2*A_SIG + s) * DDIM;
                xf[2*s]     = __ldg(xp + lane);
                xf[2*s + 1] = __ldg(xp + lane + 32);
            }
        }

        unsigned long long acc[A_SIG][2];
        #pragma unroll
        for (int s = 0; s < A_SIG; s++) { acc[s][0] = 0ull; acc[s][1] = 0ull; }

        #pragma unroll 4
        for (int d = 0; d < DDIM; d++) {
            ulonglong2 q = sDn2[d*32 + lane];
            #pragma unroll
            for (int s = 0; s < A_SIG; s++) {
                unsigned long long xd = packdup(xw[s*DDIM + d]);
                acc[s][0] = ffma2(q.x, xd, acc[s][0]);
                acc[s][1] = ffma2(q.y, xd, acc[s][1]);
            }
        }

        // store quarter-row: k = kq*128 + lane*4 + (0..3)
        #pragma unroll
        for (int s = 0; s < A_SIG; s++) {
            ulonglong2* ap = (ulonglong2*)(g_alpha0 + (size_t)(g*A_SIG + s) * KDIM + kq*KQ);
            ulonglong2 v; v.x = acc[s][0]; v.y = acc[s][1];
            ap[lane] = v;
        }
    }
}

// ---------------- Kernel B: OMP iterations, 1 signal per warp ----------------
#define B_THREADS 256
#define B_WARPS   8
#define B_BLOCKS  1024

__global__ __launch_bounds__(B_THREADS, 3)
void ompsel_kernel(float* __restrict__ out) {
    __shared__ float sAccF[2];
    __shared__ int   sHist[5];
    int tid  = threadIdx.x;
    int lane = tid & 31;
    int w    = tid >> 5;
    if (tid < 2) sAccF[tid] = 0.f;
    if (tid < 5) sHist[tid] = 0;
    __syncthreads();

    float diffacc = 0.f, zacc = 0.f;
    int h0 = 0, h1 = 0, h2 = 0, h3 = 0, h4 = 0;

    int gw = blockIdx.x * B_WARPS + w;
    #pragma unroll 1
    for (int s4 = 0; s4 < 4; s4++) {
        int n = gw * 4 + s4;
        const float4* ap = (const float4*)(g_alpha0 + (size_t)n * KDIM);
        float a0[16];
        #pragma unroll
        for (int c2 = 0; c2 < 4; c2++) {
            float4 q = __ldg(ap + c2*32 + lane);
            a0[c2*4 + 0] = q.x; a0[c2*4 + 1] = q.y;
            a0[c2*4 + 2] = q.z; a0[c2*4 + 3] = q.w;
        }
        int idx[4]; float gam[4]; float rhs[4]; float Ms[4][4];
        #pragma unroll
        for (int r = 0; r < 4; r++)
            #pragma unroll
            for (int c = 0; c < 4; c++) Ms[r][c] = 0.f;

        #pragma unroll
        for (int it = 0; it < NNZ; it++) {
            float vv[16];
            #pragma unroll
            for (int t = 0; t < 16; t++) vv[t] = a0[t];
            #pragma unroll
            for (int p = 0; p < NNZ - 1; p++) if (p < it) {
                const float4* Gr = (const float4*)(g_G + (size_t)idx[p]*KDIM);
                float gp = gam[p];
                #pragma unroll
                for (int c2 = 0; c2 < 4; c2++) {
                    float4 gq = __ldg(Gr + c2*32 + lane);
                    vv[c2*4 + 0] -= gp * gq.x;
                    vv[c2*4 + 1] -= gp * gq.y;
                    vv[c2*4 + 2] -= gp * gq.z;
                    vv[c2*4 + 3] -= gp * gq.w;
                }
            }
            float bv = -1.f; int bk = 0;
            #pragma unroll
            for (int t = 0; t < 16; t++) {
                int k = ((t >> 2) << 7) | (lane << 2) | (t & 3);
                float av = fabsf(vv[t]);
                if (av > bv) { bv = av; bk = k; }
            }
            #pragma unroll
            for (int off = 16; off > 0; off >>= 1) {
                float ov = __shfl_xor_sync(0xffffffffu, bv, off);
                int   ok = __shfl_xor_sync(0xffffffffu, bk, off);
                if (ov > bv || (ov == bv && ok < bk)) { bv = ov; bk = ok; }
            }
            idx[it] = bk;
            int tt = (((bk >> 7) & 3) << 2) | (bk & 3);
            float myv = sel16(a0, tt);
            rhs[it] = __shfl_sync(0xffffffffu, myv, (bk >> 2) & 31);
            #pragma unroll
            for (int b2 = 0; b2 < NNZ; b2++) if (b2 <= it) {
                float gv = __ldg(g_G + (size_t)bk*KDIM + idx[b2]);
                Ms[it][b2] = gv; Ms[b2][it] = gv;
            }
            {
                float M[4][4], yv[4], gv2[4];
                #pragma unroll
                for (int r = 0; r < 4; r++) {
                    #pragma unroll
                    for (int c = 0; c < 4; c++) M[r][c] = Ms[r][c];
                    M[r][r] += REGEPS;
                    yv[r] = rhs[r];
                    gv2[r] = 0.f;
                }
                #pragma unroll
                for (int c = 0; c < 4; c++) if (c <= it) {
                    float pinv = 1.f / M[c][c];
                    #pragma unroll
                    for (int r = 0; r < 4; r++) if (r > c && r <= it) {
                        float f = M[r][c] * pinv;
                        #pragma unroll
                        for (int cc = 0; cc < 4; cc++) if (cc >= c && cc <= it)
                            M[r][cc] -= f * M[c][cc];
                        yv[r] -= f * yv[c];
                    }
                }
                #pragma unroll
                for (int r = 3; r >= 0; r--) if (r <= it) {
                    float a2 = yv[r];
                    #pragma unroll
                    for (int cc = 0; cc < 4; cc++) if (cc > r && cc <= it)
                        a2 -= M[r][cc] * gv2[cc];
                    gv2[r] = a2 / M[r][r];
                }
                #pragma unroll
                for (int r = 0; r < 4; r++) if (r <= it) gam[r] = gv2[r];
            }
        }

        bool lastocc[4];
        #pragma unroll
        for (int a = 0; a < 4; a++) {
            bool lo2 = true;
            #pragma unroll
            for (int b2 = a + 1; b2 < 4; b2++) if (idx[b2] == idx[a]) lo2 = false;
            lastocc[a] = lo2;
        }
        float q0 = 0.f, q1 = 0.f;
        #pragma unroll
        for (int a = 0; a < 4; a++) if (lastocc[a]) {
            const float* dt = g_DnT + (size_t)idx[a]*DDIM;
            q0 += gam[a] * __ldg(dt + lane);
            q1 += gam[a] * __ldg(dt + lane + 32);
        }
        g_qt[(size_t)n*DDIM + lane]      = q0;
        g_qt[(size_t)n*DDIM + lane + 32] = q1;
        const float* xp = g_xt + (size_t)n * DDIM;
        float xv0 = __ldg(xp + lane);
        float xv1 = __ldg(xp + lane + 32);
        diffacc += (q0 - xv0)*(q0 - xv0) + (q1 - xv1)*(q1 - xv1);

        if (lane == 0) {
            int b = n >> 12, hw = n & 4095;
            float* ids = out + IDS_OFF + (size_t)b*(KDIM*4096) + hw;
            int cnt = 0;
            #pragma unroll
            for (int a = 0; a < 4; a++) {
                ids[(size_t)idx[a]*4096] = gam[a];
                if (lastocc[a] && gam[a] != 0.f) { cnt++; zacc += fabsf(gam[a]); }
            }
            if (cnt == 0) h0++; else if (cnt == 1) h1++; else if (cnt == 2) h2++;
            else if (cnt == 3) h3++; else h4++;
        }
    }
    #pragma unroll
    for (int off = 16; off > 0; off >>= 1) {
        diffacc += __shfl_xor_sync(0xffffffffu, diffacc, off);
        zacc    += __shfl_xor_sync(0xffffffffu, zacc, off);
    }
    if (lane == 0) {
        atomicAdd(&sAccF[0], diffacc);
        atomicAdd(&sAccF[1], zacc);
        if (h0) atomicAdd(&sHist[0], h0);
        if (h1) atomicAdd(&sHist[1], h1);
        if (h2) atomicAdd(&sHist[2], h2);
        if (h3) atomicAdd(&sHist[3], h3);
        if (h4) atomicAdd(&sHist[4], h4);
    }
    __syncthreads();
    if (tid == 0) {
        atomicAdd(&g_diffsum, sAccF[0]);
        atomicAdd(&g_zsum, sAccF[1]);
    }
    if (tid < 5) { int v = sHist[tid]; if (v) atomicAdd(&g_hist[tid], v); }
}

// ---------------- finalize scalars ----------------
__global__ void fin_kernel(float* __restrict__ out) {
    if (threadIdx.x != 0) return;
    float diff = g_diffsum / 2097152.0f;
    out[DIFF1_OFF] = diff;
    out[DIFF2_OFF] = diff;
    out[NSTEP_OFF] = 4.0f;
    out[MEAND_OFF] = g_meanDsum / 32768.0f;
    out[MEANZ_OFF] = g_zsum / 16777216.0f;
    int c0 = g_hist[0], c1 = g_hist[1], c2 = g_hist[2], c3 = g_hist[3], c4 = g_hist[4];
    float sumw = 1.f*c1 + 2.f*c2 + 3.f*c3 + 4.f*c4;
    out[NORMZ_OFF] = sumw / 32768.0f;
    const int topk = 327;
    int cum = c4; float tp = 4.f;
    if (cum < topk) { cum += c3; tp = 3.f; }
    if (cum < topk) { cum += c2; tp = 2.f; }
    if (cum < topk) { cum += c1; tp = 1.f; }
    if (cum < topk) { tp = 0.f; }
    out[TOPP_OFF]  = tp;
    out[NZERO_OFF] = (float)c0;
}

// ---------------- launch ----------------
extern "C" void kernel_launch(void* const* d_in, const int* in_sizes, int n_in,
                              void* d_out, int out_size) {
    const float* x; const float* D;
    if (in_sizes[0] == DDIM*KDIM) { D = (const float*)d_in[0]; x = (const float*)d_in[1]; }
    else                          { x = (const float*)d_in[0]; D = (const float*)d_in[1]; }
    float* out = (float*)d_out;

    cudaFuncSetAttribute(prepgram_kernel, cudaFuncAttributeMaxDynamicSharedMemorySize, DDIM*KDIM*4);
    prepgram_kernel<<<32, 256, DDIM*KDIM*4>>>(D);
    xt_kernel<<<dim3(128, 2, 8), dim3(32, 8)>>>(x);
    cudaMemsetAsync(out + IDS_OFF, 0, (size_t)16777216 * sizeof(float));
    cudaFuncSetAttribute(alpha_kernel, cudaFuncAttributeMaxDynamicSharedMemorySize, SMEM_AQ_TOTAL);
    alpha_kernel<<<456, A_THREADS, SMEM_AQ_TOTAL>>>();
    ompsel_kernel<<<B_BLOCKS, B_THREADS>>>(out);
    outt_kernel<<<dim3(128, 2, 8), dim3(32, 8)>>>(out);
    fin_kernel<<<1, 32>>>(out);
}